// round 9
// baseline (speedup 1.0000x reference)
#include <cuda_runtime.h>
#include <math.h>
#include <stdint.h>

#define BB 8
#define LL 2048
#define DD 512
#define MM 8
#define DHH 64
#define KHH 256

// ---------------- scratch (device globals; no allocations) ----------------
__device__ float g_H2[64 * 2048 * 64];
__device__ float g_T1p[16 * 64 * 64 * 64];   // [l0grp][bm][d][h] 16.8MB
__device__ float g_xsp[16 * 64 * 64];        // [l0grp][bm][d]
__device__ float g_T2[64 * 64 * 64];
__device__ float g_sb[64 * 64];
__device__ float g_mixpre[BB * LL * DD];
__device__ float g_mix[BB * LL * DD];
__device__ float g_u[BB * LL * DD];
__device__ float g_c0[BB * LL * DD];
__device__ float g_v[BB * LL * DD];
__device__ float g_w[BB * LL * DD];

__device__ __forceinline__ float geluf(float x) {
    return 0.5f * x * (1.0f + erff(x * 0.7071067811865476f));
}
__device__ __forceinline__ float sigmoidf_(float x) {
    return 1.0f / (1.0f + expf(-x));
}
__device__ __forceinline__ float pe_val(int l, int c) {
    float ang = (float)l * expf(-(float)(c & ~1) * 0.0179889460390160f);
    return (c & 1) ? cosf(ang) : sinf(ang);
}
__device__ __forceinline__ float tf32r(float x) {
    uint32_t r;
    asm("cvt.rna.tf32.f32 %0, %1;" : "=r"(r) : "f"(x));
    return __uint_as_float(r);
}
__device__ __forceinline__ void split3(float v, uint32_t& hi, uint32_t& lo) {
    uint32_t h;
    asm("cvt.rna.tf32.f32 %0, %1;" : "=r"(h) : "f"(v));
    float r = v - __uint_as_float(h);
    uint32_t l;
    asm("cvt.rna.tf32.f32 %0, %1;" : "=r"(l) : "f"(r));
    hi = h; lo = l;
}
__device__ __forceinline__ void split3f(float v, float& hi, float& lo) {
    uint32_t h, l;
    split3(v, h, l);
    hi = __uint_as_float(h); lo = __uint_as_float(l);
}
__device__ __forceinline__ void mma_tf32(float* c, const uint32_t* a, const uint32_t* b)
{
    asm volatile(
        "mma.sync.aligned.m16n8k8.row.col.f32.tf32.tf32.f32 "
        "{%0,%1,%2,%3}, {%4,%5,%6,%7}, {%8,%9}, {%0,%1,%2,%3};\n"
        : "+f"(c[0]), "+f"(c[1]), "+f"(c[2]), "+f"(c[3])
        : "r"(a[0]), "r"(a[1]), "r"(a[2]), "r"(a[3]), "r"(b[0]), "r"(b[1]));
}

// ============ kernel A: fused hyper front-end ============
// per (l0=bx*128, bm): H1 tile (smem only) -> T1 partial + xsum partial -> H2 tile (global)
__global__ void __launch_bounds__(256)
fc1_mma(const float* __restrict__ x,
        const float* __restrict__ f1w_1, const float* __restrict__ f1b_1,
        const float* __restrict__ f1w_2, const float* __restrict__ f1b_2)
{
    extern __shared__ float sm[];
    float* Xs  = sm;                 // [128][68] x + pe
    float* Xr  = Xs + 128 * 68;      // [128][68] raw x
    float* H1s = Xr + 128 * 68;      // [128][68] H1 tile / H2 staging
    float* W1s = H1s + 128 * 68;     // [64][68]
    float* W2s = W1s + 64 * 68;      // [64][68]
    float* b1s = W2s + 64 * 68;      // 64
    float* b2s = b1s + 64;           // 64
    float* xps = b2s + 64;           // 256
    int tid = threadIdx.x;
    int l0 = blockIdx.x * 128;
    int bm = blockIdx.y;
    int b = bm >> 3, m = bm & 7;

    {
        int f4 = (tid & 15) * 4, r = tid >> 4;
#pragma unroll
        for (int it = 0; it < 8; it++) {
            int row = r + it * 16;
            int l = l0 + row;
            float4 v = *(const float4*)&x[(size_t)(b * LL + l) * DD + m * 64 + f4];
            Xr[row * 68 + f4 + 0] = v.x;
            Xr[row * 68 + f4 + 1] = v.y;
            Xr[row * 68 + f4 + 2] = v.z;
            Xr[row * 68 + f4 + 3] = v.w;
            Xs[row * 68 + f4 + 0] = v.x + pe_val(l, m * 64 + f4 + 0);
            Xs[row * 68 + f4 + 1] = v.y + pe_val(l, m * 64 + f4 + 1);
            Xs[row * 68 + f4 + 2] = v.z + pe_val(l, m * 64 + f4 + 2);
            Xs[row * 68 + f4 + 3] = v.w + pe_val(l, m * 64 + f4 + 3);
        }
#pragma unroll
        for (int it = 0; it < 4; it++) {
            int hh = r + it * 16;
            *(float4*)&W1s[hh * 68 + f4] = *(const float4*)&f1w_1[m * 4096 + hh * 64 + f4];
            *(float4*)&W2s[hh * 68 + f4] = *(const float4*)&f1w_2[m * 4096 + hh * 64 + f4];
        }
        if (tid < 64) { b1s[tid] = f1b_1[m * 64 + tid]; b2s[tid] = f1b_2[m * 64 + tid]; }
    }
    __syncthreads();

    int warp = tid >> 5, lane = tid & 31, gid = lane >> 2, tig = lane & 3;
    int mw = warp & 3, nw = warp >> 2;
    int rb = mw * 32, vb = nw * 32;

    // ---- mainloop 0: H1 = gelu(Xs @ W1^T + b1) ----
    {
        float acc[2][4][4] = {};
#pragma unroll
        for (int kk = 0; kk < 64; kk += 8) {
            uint32_t ah[2][4], al[2][4];
#pragma unroll
            for (int mi = 0; mi < 2; mi++) {
                int rr = rb + mi * 16;
                split3(Xs[(rr + gid) * 68 + kk + tig],     ah[mi][0], al[mi][0]);
                split3(Xs[(rr + gid + 8) * 68 + kk + tig], ah[mi][1], al[mi][1]);
                split3(Xs[(rr + gid) * 68 + kk + tig + 4],     ah[mi][2], al[mi][2]);
                split3(Xs[(rr + gid + 8) * 68 + kk + tig + 4], ah[mi][3], al[mi][3]);
            }
            uint32_t bh[4][2], bl[4][2];
#pragma unroll
            for (int ni = 0; ni < 4; ni++) {
                int cc = vb + ni * 8 + gid;
                split3(W1s[cc * 68 + kk + tig],     bh[ni][0], bl[ni][0]);
                split3(W1s[cc * 68 + kk + tig + 4], bh[ni][1], bl[ni][1]);
            }
#pragma unroll
            for (int mi = 0; mi < 2; mi++)
#pragma unroll
                for (int ni = 0; ni < 4; ni++) {
                    mma_tf32(acc[mi][ni], ah[mi], bh[ni]);
                    mma_tf32(acc[mi][ni], ah[mi], bl[ni]);
                    mma_tf32(acc[mi][ni], al[mi], bh[ni]);
                }
        }
        // epilogue -> H1s (full 128 rows, disjoint per warp)
#pragma unroll
        for (int mi = 0; mi < 2; mi++)
#pragma unroll
            for (int ni = 0; ni < 4; ni++) {
                int rr = rb + mi * 16 + gid;
                int cc = vb + ni * 8 + tig * 2;
                H1s[rr * 68 + cc]           = geluf(acc[mi][ni][0] + b1s[cc]);
                H1s[rr * 68 + cc + 1]       = geluf(acc[mi][ni][1] + b1s[cc + 1]);
                H1s[(rr + 8) * 68 + cc]     = geluf(acc[mi][ni][2] + b1s[cc]);
                H1s[(rr + 8) * 68 + cc + 1] = geluf(acc[mi][ni][3] + b1s[cc + 1]);
            }
    }
    __syncthreads();

    // ---- T1 partial = Xr^T @ H1s  (K = 128 l-rows) ----
    {
        int rbT = (warp & 3) * 16, vbT = (warp >> 2) * 32;
        float t1acc[4][4] = {};
        for (int kk = 0; kk < 128; kk += 8) {
            uint32_t ah[4], al[4];
            split3(Xr[(kk + tig) * 68 + rbT + gid],         ah[0], al[0]);
            split3(Xr[(kk + tig) * 68 + rbT + gid + 8],     ah[1], al[1]);
            split3(Xr[(kk + tig + 4) * 68 + rbT + gid],     ah[2], al[2]);
            split3(Xr[(kk + tig + 4) * 68 + rbT + gid + 8], ah[3], al[3]);
            uint32_t bh[4][2], bl[4][2];
#pragma unroll
            for (int ni = 0; ni < 4; ni++) {
                int cc = vbT + ni * 8 + gid;
                split3(H1s[(kk + tig) * 68 + cc],     bh[ni][0], bl[ni][0]);
                split3(H1s[(kk + tig + 4) * 68 + cc], bh[ni][1], bl[ni][1]);
            }
#pragma unroll
            for (int ni = 0; ni < 4; ni++) {
                mma_tf32(t1acc[ni], ah, bh[ni]);
                mma_tf32(t1acc[ni], ah, bl[ni]);
                mma_tf32(t1acc[ni], al, bh[ni]);
            }
        }
        size_t baseT = ((size_t)(blockIdx.x * 64 + bm)) * 4096;
#pragma unroll
        for (int ni = 0; ni < 4; ni++) {
            int d0 = rbT + gid, h = vbT + ni * 8 + tig * 2;
            float2 v0 = {t1acc[ni][0], t1acc[ni][1]};
            float2 v1 = {t1acc[ni][2], t1acc[ni][3]};
            *(float2*)&g_T1p[baseT + (size_t)d0 * 64 + h] = v0;
            *(float2*)&g_T1p[baseT + (size_t)(d0 + 8) * 64 + h] = v1;
        }
    }

    // ---- xsum partial from Xr ----
    {
        int d = tid & 63, q = tid >> 6;
        float s = 0.f;
#pragma unroll 8
        for (int r = 0; r < 32; r++) s += Xr[(q * 32 + r) * 68 + d];
        xps[tid] = s;
    }
    __syncthreads();
    if (tid < 64)
        g_xsp[((size_t)(blockIdx.x * 64 + bm)) * 64 + tid] =
            xps[tid] + xps[64 + tid] + xps[128 + tid] + xps[192 + tid];

    // ---- mainloop 1: H2 = gelu(Xs @ W2^T + b2) -> global (staged via H1s) ----
    {
        float acc[2][4][4] = {};
#pragma unroll
        for (int kk = 0; kk < 64; kk += 8) {
            uint32_t ah[2][4], al[2][4];
#pragma unroll
            for (int mi = 0; mi < 2; mi++) {
                int rr = rb + mi * 16;
                split3(Xs[(rr + gid) * 68 + kk + tig],     ah[mi][0], al[mi][0]);
                split3(Xs[(rr + gid + 8) * 68 + kk + tig], ah[mi][1], al[mi][1]);
                split3(Xs[(rr + gid) * 68 + kk + tig + 4],     ah[mi][2], al[mi][2]);
                split3(Xs[(rr + gid + 8) * 68 + kk + tig + 4], ah[mi][3], al[mi][3]);
            }
            uint32_t bh[4][2], bl[4][2];
#pragma unroll
            for (int ni = 0; ni < 4; ni++) {
                int cc = vb + ni * 8 + gid;
                split3(W2s[cc * 68 + kk + tig],     bh[ni][0], bl[ni][0]);
                split3(W2s[cc * 68 + kk + tig + 4], bh[ni][1], bl[ni][1]);
            }
#pragma unroll
            for (int mi = 0; mi < 2; mi++)
#pragma unroll
                for (int ni = 0; ni < 4; ni++) {
                    mma_tf32(acc[mi][ni], ah[mi], bh[ni]);
                    mma_tf32(acc[mi][ni], ah[mi], bl[ni]);
                    mma_tf32(acc[mi][ni], al[mi], bh[ni]);
                }
        }
        __syncthreads();   // all T1/H1s reads complete before overwrite
#pragma unroll
        for (int mi = 0; mi < 2; mi++)
#pragma unroll
            for (int ni = 0; ni < 4; ni++) {
                int rr = rb + mi * 16 + gid;
                int cc = vb + ni * 8 + tig * 2;
                H1s[rr * 68 + cc]           = geluf(acc[mi][ni][0] + b2s[cc]);
                H1s[rr * 68 + cc + 1]       = geluf(acc[mi][ni][1] + b2s[cc + 1]);
                H1s[(rr + 8) * 68 + cc]     = geluf(acc[mi][ni][2] + b2s[cc]);
                H1s[(rr + 8) * 68 + cc + 1] = geluf(acc[mi][ni][3] + b2s[cc + 1]);
            }
        __syncthreads();
#pragma unroll
        for (int it = 0; it < 8; it++) {
            int idx = tid + 256 * it;
            int row = idx >> 4, c4 = (idx & 15) * 4;
            *(float4*)&g_H2[((size_t)bm * LL + l0 + row) * 64 + c4] =
                *(float4*)&H1s[row * 68 + c4];
        }
    }
}

// ============ kernel C: T1 reduce; S = gelu(...); T2 = S fc2_2; sb = S.b2_2 ============
__global__ void __launch_bounds__(256)
sgen_kernel(const float* __restrict__ f2w1, const float* __restrict__ f2b1,
            const float* __restrict__ f2w2, const float* __restrict__ f2b2)
{
    extern __shared__ float sm[];
    float* T1s  = sm;
    float* F1s  = T1s + 4160;
    float* F2s  = F1s + 4160;
    float* Ss   = F2s + 4160;
    float* xsums= Ss + 4160;
    float* b1s  = xsums + 64;
    float* b2s  = b1s + 64;
    int tid = threadIdx.x;
    int bm = blockIdx.x;
    int m = bm & 7;

#pragma unroll
    for (int r = 0; r < 16; r++) {
        int o = tid + 256 * r;
        float s = 0.f;
#pragma unroll
        for (int g = 0; g < 16; g++)
            s += g_T1p[((size_t)(g * 64 + bm)) * 4096 + o];
        T1s[(o >> 6) * 65 + (o & 63)] = s;
    }
    if (tid < 64) {
        float s = 0.f;
#pragma unroll
        for (int g = 0; g < 16; g++)
            s += g_xsp[((size_t)(g * 64 + bm)) * 64 + tid];
        xsums[tid] = s;
    }
    __syncthreads();

    int tx = tid & 15, ty = tid >> 4;
    float t2acc[4][4] = {};
    float sbacc[4] = {};
    for (int c = 0; c < 4; c++) {
        __syncthreads();
#pragma unroll
        for (int r = 0; r < 16; r++) {
            int i = tid + 256 * r;
            int khl = i >> 6, h = i & 63;
            F1s[khl * 65 + h] = f2w1[(size_t)m * 16384 + (c * 64 + khl) * 64 + h];
            F2s[khl * 65 + h] = f2w2[(size_t)m * 16384 + (c * 64 + khl) * 64 + h];
        }
        if (tid < 64) {
            b1s[tid] = f2b1[m * 256 + c * 64 + tid];
            b2s[tid] = f2b2[m * 256 + c * 64 + tid];
        }
        __syncthreads();
        float spre[4][4] = {};
#pragma unroll 8
        for (int h = 0; h < 64; h++) {
            float tv[4], fv[4];
#pragma unroll
            for (int ii = 0; ii < 4; ii++) tv[ii] = T1s[(ty * 4 + ii) * 65 + h];
#pragma unroll
            for (int jj = 0; jj < 4; jj++) fv[jj] = F1s[(tx * 4 + jj) * 65 + h];
#pragma unroll
            for (int ii = 0; ii < 4; ii++)
#pragma unroll
                for (int jj = 0; jj < 4; jj++)
                    spre[ii][jj] += tv[ii] * fv[jj];
        }
#pragma unroll
        for (int ii = 0; ii < 4; ii++)
#pragma unroll
            for (int jj = 0; jj < 4; jj++) {
                int d = ty * 4 + ii, khl = tx * 4 + jj;
                Ss[d * 65 + khl] = geluf(spre[ii][jj] + xsums[d] * b1s[khl]);
            }
        __syncthreads();
#pragma unroll 8
        for (int khl = 0; khl < 64; khl++) {
            float sv[4], fv[4];
#pragma unroll
            for (int ii = 0; ii < 4; ii++) sv[ii] = Ss[(ty * 4 + ii) * 65 + khl];
#pragma unroll
            for (int jj = 0; jj < 4; jj++) fv[jj] = F2s[khl * 65 + tx * 4 + jj];
#pragma unroll
            for (int ii = 0; ii < 4; ii++)
#pragma unroll
                for (int jj = 0; jj < 4; jj++)
                    t2acc[ii][jj] += sv[ii] * fv[jj];
            if (tx == 0) {
                float bv = b2s[khl];
#pragma unroll
                for (int ii = 0; ii < 4; ii++) sbacc[ii] += sv[ii] * bv;
            }
        }
    }
#pragma unroll
    for (int ii = 0; ii < 4; ii++)
#pragma unroll
        for (int jj = 0; jj < 4; jj++)
            g_T2[(size_t)bm * 4096 + (ty * 4 + ii) * 64 + tx * 4 + jj] = t2acc[ii][jj];
    if (tx == 0)
#pragma unroll
        for (int ii = 0; ii < 4; ii++) g_sb[bm * 64 + ty * 4 + ii] = sbacc[ii];
}

// ============ kernel E: mixpre = H2 @ T2^T + sb — 3xTF32, hi/lo hoisted ============
__global__ void __launch_bounds__(256)
mixpre_mma()
{
    extern __shared__ float sm[];
    float* Hh  = sm;                // [128][68]
    float* Hl  = Hh + 128 * 68;     // [128][68]
    float* Th  = Hl + 128 * 68;     // [64][68]  (reused as Cs in epilogue)
    float* Tl  = Th + 64 * 68;      // [64][68]
    float* sbs = Tl + 64 * 68;      // 64
    float* Cs  = Th;
    int tid = threadIdx.x;
    int l0 = blockIdx.x * 128;
    int bm = blockIdx.y;
    int b = bm >> 3, m = bm & 7;

    {
        int f4 = (tid & 15) * 4, r = tid >> 4;
#pragma unroll
        for (int it = 0; it < 8; it++) {
            int row = r + it * 16;
            float4 v = *(const float4*)&g_H2[((size_t)bm * LL + l0 + row) * 64 + f4];
            split3f(v.x, Hh[row * 68 + f4 + 0], Hl[row * 68 + f4 + 0]);
            split3f(v.y, Hh[row * 68 + f4 + 1], Hl[row * 68 + f4 + 1]);
            split3f(v.z, Hh[row * 68 + f4 + 2], Hl[row * 68 + f4 + 2]);
            split3f(v.w, Hh[row * 68 + f4 + 3], Hl[row * 68 + f4 + 3]);
        }
#pragma unroll
        for (int it = 0; it < 4; it++) {
            int dd = r + it * 16;
            float4 v = *(const float4*)&g_T2[(size_t)bm * 4096 + dd * 64 + f4];
            split3f(v.x, Th[dd * 68 + f4 + 0], Tl[dd * 68 + f4 + 0]);
            split3f(v.y, Th[dd * 68 + f4 + 1], Tl[dd * 68 + f4 + 1]);
            split3f(v.z, Th[dd * 68 + f4 + 2], Tl[dd * 68 + f4 + 2]);
            split3f(v.w, Th[dd * 68 + f4 + 3], Tl[dd * 68 + f4 + 3]);
        }
        if (tid < 64) sbs[tid] = g_sb[bm * 64 + tid];
    }
    __syncthreads();

    int warp = tid >> 5, lane = tid & 31, gid = lane >> 2, tig = lane & 3;
    int mw = warp & 3, nw = warp >> 2;
    int rb = mw * 32, vb = nw * 32;

    float acc[2][4][4] = {};
#pragma unroll
    for (int kk = 0; kk < 64; kk += 8) {
        uint32_t ah[2][4], al[2][4];
#pragma unroll
        for (int mi = 0; mi < 2; mi++) {
            int rr = rb + mi * 16;
            ah[mi][0] = __float_as_uint(Hh[(rr + gid) * 68 + kk + tig]);
            al[mi][0] = __float_as_uint(Hl[(rr + gid) * 68 + kk + tig]);
            ah[mi][1] = __float_as_uint(Hh[(rr + gid + 8) * 68 + kk + tig]);
            al[mi][1] = __float_as_uint(Hl[(rr + gid + 8) * 68 + kk + tig]);
            ah[mi][2] = __float_as_uint(Hh[(rr + gid) * 68 + kk + tig + 4]);
            al[mi][2] = __float_as_uint(Hl[(rr + gid) * 68 + kk + tig + 4]);
            ah[mi][3] = __float_as_uint(Hh[(rr + gid + 8) * 68 + kk + tig + 4]);
            al[mi][3] = __float_as_uint(Hl[(rr + gid + 8) * 68 + kk + tig + 4]);
        }
        uint32_t bh[4][2], bl[4][2];
#pragma unroll
        for (int ni = 0; ni < 4; ni++) {
            int cc = vb + ni * 8 + gid;
            bh[ni][0] = __float_as_uint(Th[cc * 68 + kk + tig]);
            bl[ni][0] = __float_as_uint(Tl[cc * 68 + kk + tig]);
            bh[ni][1] = __float_as_uint(Th[cc * 68 + kk + tig + 4]);
            bl[ni][1] = __float_as_uint(Tl[cc * 68 + kk + tig + 4]);
        }
#pragma unroll
        for (int mi = 0; mi < 2; mi++)
#pragma unroll
            for (int ni = 0; ni < 4; ni++) {
                mma_tf32(acc[mi][ni], ah[mi], bh[ni]);
                mma_tf32(acc[mi][ni], ah[mi], bl[ni]);
                mma_tf32(acc[mi][ni], al[mi], bh[ni]);
            }
    }
    __syncthreads();   // tile reads done before Cs overlays Th
#pragma unroll
    for (int p = 0; p < 2; p++) {
        if ((mw >> 1) == p) {
            int lr = (mw & 1) * 32;
#pragma unroll
            for (int mi = 0; mi < 2; mi++)
#pragma unroll
                for (int ni = 0; ni < 4; ni++) {
                    int rr = lr + mi * 16 + gid;
                    int cc = vb + ni * 8 + tig * 2;
                    Cs[rr * 68 + cc]           = acc[mi][ni][0] + sbs[cc];
                    Cs[rr * 68 + cc + 1]       = acc[mi][ni][1] + sbs[cc + 1];
                    Cs[(rr + 8) * 68 + cc]     = acc[mi][ni][2] + sbs[cc];
                    Cs[(rr + 8) * 68 + cc + 1] = acc[mi][ni][3] + sbs[cc + 1];
                }
        }
        __syncthreads();
#pragma unroll
        for (int it = 0; it < 4; it++) {
            int idx = tid + 256 * it;
            int row = idx >> 4, c4 = (idx & 15) * 4;
            *(float4*)&g_mixpre[(size_t)(b * LL + l0 + p * 64 + row) * DD + m * 64 + c4] =
                *(float4*)&Cs[row * 68 + c4];
        }
        __syncthreads();
    }
}

// ---------------- LN helpers ----------------
__device__ __forceinline__ float blk_sum128(float v, float* sbuf)
{
#pragma unroll
    for (int o = 16; o; o >>= 1) v += __shfl_xor_sync(0xffffffffu, v, o);
    __syncthreads();
    if ((threadIdx.x & 31) == 0) sbuf[threadIdx.x >> 5] = v;
    __syncthreads();
    return sbuf[0] + sbuf[1] + sbuf[2] + sbuf[3];
}

__global__ void __launch_bounds__(128)
ln_mix_kernel(const float* __restrict__ g1, const float* __restrict__ b1,
              const float* __restrict__ g2, const float* __restrict__ b2)
{
    __shared__ float sbuf[4];
    size_t row = blockIdx.x;
    int t = threadIdx.x;
    const float* r = g_mixpre + row * DD;
    float v[4];
#pragma unroll
    for (int i = 0; i < 4; i++) v[i] = r[t + 128 * i];
    float mean = blk_sum128(v[0] + v[1] + v[2] + v[3], sbuf) * (1.0f / 512.0f);
    float sq = 0.f;
#pragma unroll
    for (int i = 0; i < 4; i++) { float d = v[i] - mean; sq += d * d; }
    float var = blk_sum128(sq, sbuf) * (1.0f / 512.0f);
    float inv = rsqrtf(var + 1e-5f);
    float mx[4];
#pragma unroll
    for (int i = 0; i < 4; i++) {
        int c = t + 128 * i;
        mx[i] = (v[i] - mean) * inv * g1[c] + b1[c];
        g_mix[row * DD + c] = mx[i];
    }
    float mean2 = blk_sum128(mx[0] + mx[1] + mx[2] + mx[3], sbuf) * (1.0f / 512.0f);
    float sq2 = 0.f;
#pragma unroll
    for (int i = 0; i < 4; i++) { float d = mx[i] - mean2; sq2 += d * d; }
    float var2 = blk_sum128(sq2, sbuf) * (1.0f / 512.0f);
    float inv2 = rsqrtf(var2 + 1e-5f);
#pragma unroll
    for (int i = 0; i < 4; i++) {
        int c = t + 128 * i;
        g_u[row * DD + c] = (mx[i] - mean2) * inv2 * g2[c] + b2[c];
    }
}

// ============ bottleneck 1x1 + GLU via tf32 mma — double-buffered ============
__global__ void __launch_bounds__(256)
bneck_glu_mma(const float* __restrict__ bw, const float* __restrict__ bb)
{
    __shared__ float As[2][16][132];
    __shared__ float Bs[2][16][132];
    __shared__ float Cs[32][68];
    int tid = threadIdx.x;
    int warp = tid >> 5, lane = tid & 31;
    int mw = warp & 3, nw = warp >> 2;
    int gid = lane >> 2, tig = lane & 3;
    int r0 = blockIdx.y * 128, n0 = blockIdx.x * 64;

    float acc[2][8][4] = {};

    int arow = tid >> 1;
    int akq  = (tid & 1) * 8;
    int vcol = tid >> 1;
    int brr  = (vcol & 1) ? (512 + n0 + (vcol >> 1)) : (n0 + (vcol >> 1));

    const float* pA = &g_u[(size_t)(r0 + arow) * 512 + akq];
    const float* pB = &bw[(size_t)brr * 512 + akq];

    float ar[8], br[8];
    *(float4*)&ar[0] = *(const float4*)pA;
    *(float4*)&ar[4] = *(const float4*)(pA + 4);
    *(float4*)&br[0] = *(const float4*)pB;
    *(float4*)&br[4] = *(const float4*)(pB + 4);
#pragma unroll
    for (int j = 0; j < 8; j++) {
        As[0][akq + j][arow] = tf32r(ar[j]);
        Bs[0][akq + j][vcol] = tf32r(br[j]);
    }
    __syncthreads();

    for (int t = 0; t < 32; t++) {
        int cur = t & 1;
        if (t < 31) {
            const float* qA = pA + (t + 1) * 16;
            const float* qB = pB + (t + 1) * 16;
            *(float4*)&ar[0] = *(const float4*)qA;
            *(float4*)&ar[4] = *(const float4*)(qA + 4);
            *(float4*)&br[0] = *(const float4*)qB;
            *(float4*)&br[4] = *(const float4*)(qB + 4);
        }
#pragma unroll
        for (int kk = 0; kk < 16; kk += 8) {
            uint32_t a[2][4];
#pragma unroll
            for (int mi = 0; mi < 2; mi++) {
                int rb = mw * 32 + mi * 16;
                a[mi][0] = __float_as_uint(As[cur][kk + tig][rb + gid]);
                a[mi][1] = __float_as_uint(As[cur][kk + tig][rb + gid + 8]);
                a[mi][2] = __float_as_uint(As[cur][kk + tig + 4][rb + gid]);
                a[mi][3] = __float_as_uint(As[cur][kk + tig + 4][rb + gid + 8]);
            }
            uint32_t bfr[8][2];
#pragma unroll
            for (int ni = 0; ni < 8; ni++) {
                int vb = nw * 64 + ni * 8;
                bfr[ni][0] = __float_as_uint(Bs[cur][kk + tig][vb + gid]);
                bfr[ni][1] = __float_as_uint(Bs[cur][kk + tig + 4][vb + gid]);
            }
#pragma unroll
            for (int mi = 0; mi < 2; mi++)
#pragma unroll
                for (int ni = 0; ni < 8; ni++)
                    mma_tf32(acc[mi][ni], a[mi], bfr[ni]);
        }
        if (t < 31) {
#pragma unroll
            for (int j = 0; j < 8; j++) {
                As[cur ^ 1][akq + j][arow] = tf32r(ar[j]);
                Bs[cur ^ 1][akq + j][vcol] = tf32r(br[j]);
            }
        }
        __syncthreads();
    }

    float bbA[8], bbB[8];
#pragma unroll
    for (int ni = 0; ni < 8; ni++) {
        int cR = n0 + nw * 32 + ni * 4 + tig;
        bbA[ni] = bb[cR];
        bbB[ni] = bb[512 + cR];
    }
    for (int p = 0; p < 4; p++) {
        if (mw == p) {
#pragma unroll
            for (int mi = 0; mi < 2; mi++)
#pragma unroll
                for (int ni = 0; ni < 8; ni++) {
                    int cc = nw * 32 + ni * 4 + tig;
                    float ga0 = acc[mi][ni][0] + bbA[ni];
                    float gb0 = acc[mi][ni][1] + bbB[ni];
                    float ga1 = acc[mi][ni][2] + bbA[ni];
                    float gb1 = acc[mi][ni][3] + bbB[ni];
                    Cs[mi * 16 + gid][cc]     = ga0 * sigmoidf_(gb0);
                    Cs[mi * 16 + gid + 8][cc] = ga1 * sigmoidf_(gb1);
                }
        }
        __syncthreads();
        {
            int row = tid >> 3, c = (tid & 7) * 8;
            float4 v0 = *(float4*)&Cs[row][c];
            float4 v1 = *(float4*)&Cs[row][c + 4];
            float* op = &g_c0[(size_t)(r0 + p * 32 + row) * 512 + n0 + c];
            *(float4*)op = v0;
            *(float4*)(op + 4) = v1;
        }
        __syncthreads();
    }
}

// ============ depthwise conv (K=31, pad 15) — register sliding window ============
__global__ void __launch_bounds__(256)
dwconv_kernel(const float* __restrict__ dw, const float* __restrict__ dwb)
{
    __shared__ float ins[158 * 64];
    __shared__ float wts[64 * 31];
    __shared__ float bs[64];
    int tid = threadIdx.x;
    int c0 = blockIdx.x * 64;
    int l0 = blockIdx.y * 128;
    int b  = blockIdx.z;
    for (int i = tid; i < 158 * 64; i += 256) {
        int rr = i >> 6, c = i & 63;
        int l = l0 - 15 + rr;
        ins[i] = (l >= 0 && l < LL) ? g_c0[((size_t)(b * LL + l)) * DD + c0 + c] : 0.f;
    }
    for (int i = tid; i < 64 * 31; i += 256)
        wts[i] = dw[c0 * 31 + i];
    if (tid < 64) bs[tid] = dwb[c0 + tid];
    __syncthreads();
    int tx = tid & 63, ty = tid >> 6;
    float w[31];
#pragma unroll
    for (int j = 0; j < 31; j++) w[j] = wts[tx * 31 + j];
    float bias = bs[tx];
    int base = ty * 32;
    float win[31];
#pragma unroll
    for (int j = 0; j < 30; j++) win[j] = ins[(base + j) * 64 + tx];
#pragma unroll
    for (int li = 0; li < 32; li++) {
        win[30] = ins[(base + li + 30) * 64 + tx];
        float acc = bias;
#pragma unroll
        for (int j = 0; j < 31; j++) acc += win[j] * w[j];
        g_v[((size_t)(b * LL + l0 + base + li)) * DD + c0 + tx] = acc;
#pragma unroll
        for (int j = 0; j < 30; j++) win[j] = win[j + 1];
    }
}

// ============ LN2 + gelu ============
__global__ void __launch_bounds__(128)
ln2_gelu_kernel(const float* __restrict__ g2, const float* __restrict__ b2)
{
    __shared__ float sbuf[4];
    size_t row = blockIdx.x;
    int t = threadIdx.x;
    const float* r = g_v + row * DD;
    float v[4];
#pragma unroll
    for (int i = 0; i < 4; i++) v[i] = r[t + 128 * i];
    float mean = blk_sum128(v[0] + v[1] + v[2] + v[3], sbuf) * (1.0f / 512.0f);
    float sq = 0.f;
#pragma unroll
    for (int i = 0; i < 4; i++) { float d = v[i] - mean; sq += d * d; }
    float var = blk_sum128(sq, sbuf) * (1.0f / 512.0f);
    float inv = rsqrtf(var + 1e-5f);
#pragma unroll
    for (int i = 0; i < 4; i++) {
        int c = t + 128 * i;
        g_w[row * DD + c] = geluf((v[i] - mean) * inv * g2[c] + b2[c]);
    }
}

// ============ final linear + bias + residual via tf32 mma — double-buffered ============
__global__ void __launch_bounds__(256)
linear_res_mma(const float* __restrict__ lw, const float* __restrict__ lb,
               float* __restrict__ out)
{
    extern __shared__ float smd[];
    float* Asd = smd;
    float* Bsd = smd + 4224;
    float* Csd = smd + 8448;
#define LAS(bf, k, r) Asd[(bf) * 2112 + (k) * 132 + (r)]
#define LBS(bf, k, r) Bsd[(bf) * 2112 + (k) * 132 + (r)]
    int tid = threadIdx.x;
    int warp = tid >> 5, lane = tid & 31;
    int mw = warp & 3, nw = warp >> 2;
    int gid = lane >> 2, tig = lane & 3;
    int r0 = blockIdx.y * 128, n0 = blockIdx.x * 128;

    float acc[2][8][4] = {};

    int arow = tid >> 1;
    int akq  = (tid & 1) * 8;

    const float* pA = &g_w[(size_t)(r0 + arow) * 512 + akq];
    const float* pB = &lw[(size_t)(n0 + arow) * 512 + akq];

    float ar[8], br[8];
    *(float4*)&ar[0] = *(const float4*)pA;
    *(float4*)&ar[4] = *(const float4*)(pA + 4);
    *(float4*)&br[0] = *(const float4*)pB;
    *(float4*)&br[4] = *(const float4*)(pB + 4);
#pragma unroll
    for (int j = 0; j < 8; j++) {
        LAS(0, akq + j, arow) = tf32r(ar[j]);
        LBS(0, akq + j, arow) = tf32r(br[j]);
    }
    __syncthreads();

    for (int t = 0; t < 32; t++) {
        int cur = t & 1;
        if (t < 31) {
            const float* qA = pA + (t + 1) * 16;
            const float* qB = pB + (t + 1) * 16;
            *(float4*)&ar[0] = *(const float4*)qA;
            *(float4*)&ar[4] = *(const float4*)(qA + 4);
            *(float4*)&br[0] = *(const float4*)qB;
            *(float4*)&br[4] = *(const float4*)(qB + 4);
        }
#pragma unroll
        for (int kk = 0; kk < 16; kk += 8) {
            uint32_t a[2][4];
#pragma unroll
            for (int mi = 0; mi < 2; mi++) {
                int rb = mw * 32 + mi * 16;
                a[mi][0] = __float_as_uint(LAS(cur, kk + tig, rb + gid));
                a[mi][1] = __float_as_uint(LAS(cur, kk + tig, rb + gid + 8));
                a[mi][2] = __float_as_uint(LAS(cur, kk + tig + 4, rb + gid));
                a[mi][3] = __float_as_uint(LAS(cur, kk + tig + 4, rb + gid + 8));
            }
            uint32_t bfr[8][2];
#pragma unroll
            for (int ni = 0; ni < 8; ni++) {
                int vb = nw * 64 + ni * 8;
                bfr[ni][0] = __float_as_uint(LBS(cur, kk + tig, vb + gid));
                bfr[ni][1] = __float_as_uint(LBS(cur, kk + tig + 4, vb + gid));
            }
#pragma unroll
            for (int mi = 0; mi < 2; mi++)
#pragma unroll
                for (int ni = 0; ni < 8; ni++)
                    mma_tf32(acc[mi][ni], a[mi], bfr[ni]);
        }
        if (t < 31) {
#pragma unroll
            for (int j = 0; j < 8; j++) {
                LAS(cur ^ 1, akq + j, arow) = tf32r(ar[j]);
                LBS(cur ^ 1, akq + j, arow) = tf32r(br[j]);
            }
        }
        __syncthreads();
    }

    for (int p = 0; p < 4; p++) {
        if (mw == p) {
#pragma unroll
            for (int mi = 0; mi < 2; mi++)
#pragma unroll
                for (int ni = 0; ni < 8; ni++) {
                    int cc = nw * 64 + ni * 8 + tig * 2;
                    Csd[(mi * 16 + gid) * 132 + cc]         = acc[mi][ni][0];
                    Csd[(mi * 16 + gid) * 132 + cc + 1]     = acc[mi][ni][1];
                    Csd[(mi * 16 + gid + 8) * 132 + cc]     = acc[mi][ni][2];
                    Csd[(mi * 16 + gid + 8) * 132 + cc + 1] = acc[mi][ni][3];
                }
        }
        __syncthreads();
        {
            int row = tid >> 3, c0c = (tid & 7) * 16;
            size_t gro = (size_t)(r0 + p * 32 + row) * 512 + n0;
#pragma unroll
            for (int q = 0; q < 4; q++) {
                int c = c0c + q * 4;
                float4 v = *(float4*)&Csd[row * 132 + c];
                float4 mres = *(const float4*)&g_mix[gro + c];
                float4 bl = *(const float4*)&lb[n0 + c];
                v.x += bl.x + mres.x; v.y += bl.y + mres.y;
                v.z += bl.z + mres.z; v.w += bl.w + mres.w;
                *(float4*)&out[gro + c] = v;
            }
        }
        __syncthreads();
    }
#undef LAS
#undef LBS
}

// ---------------- launch ----------------
extern "C" void kernel_launch(void* const* d_in, const int* in_sizes, int n_in,
                              void* d_out, int out_size)
{
    (void)in_sizes; (void)n_in; (void)out_size;
    const float* x      = (const float*)d_in[0];
    const float* w1f1w  = (const float*)d_in[1];
    const float* w1f1b  = (const float*)d_in[2];
    const float* w1f2w  = (const float*)d_in[3];
    const float* w1f2b  = (const float*)d_in[4];
    const float* w2f1w  = (const float*)d_in[5];
    const float* w2f1b  = (const float*)d_in[6];
    const float* w2f2w  = (const float*)d_in[7];
    const float* w2f2b  = (const float*)d_in[8];
    const float* lnmg   = (const float*)d_in[9];
    const float* lnmb   = (const float*)d_in[10];
    const float* c1g    = (const float*)d_in[11];
    const float* c1b    = (const float*)d_in[12];
    const float* bw     = (const float*)d_in[13];
    const float* bb     = (const float*)d_in[14];
    const float* dww    = (const float*)d_in[15];
    const float* dwb    = (const float*)d_in[16];
    const float* c2g    = (const float*)d_in[17];
    const float* c2b    = (const float*)d_in[18];
    const float* lw     = (const float*)d_in[19];
    const float* lb     = (const float*)d_in[20];
    float* out = (float*)d_out;

    const int SGEN_SMEM = (4 * 4160 + 64 + 64 + 64) * 4;
    const int FC1_SMEM  = (3 * 128 * 68 + 2 * 64 * 68 + 64 + 64 + 256) * 4;   // ~140.8KB
    const int MIX_SMEM  = (2 * 128 * 68 + 2 * 64 * 68 + 64) * 4;              // ~104.7KB
    const int LIN_SMEM  = (2 * 2112 * 2 + 32 * 132) * 4;
    cudaFuncSetAttribute(sgen_kernel, cudaFuncAttributeMaxDynamicSharedMemorySize, SGEN_SMEM);
    cudaFuncSetAttribute(fc1_mma, cudaFuncAttributeMaxDynamicSharedMemorySize, FC1_SMEM);
    cudaFuncSetAttribute(mixpre_mma, cudaFuncAttributeMaxDynamicSharedMemorySize, MIX_SMEM);
    cudaFuncSetAttribute(linear_res_mma, cudaFuncAttributeMaxDynamicSharedMemorySize, LIN_SMEM);

    fc1_mma<<<dim3(16, 64), 256, FC1_SMEM>>>(x, w1f1w, w1f1b, w2f1w, w2f1b);
    sgen_kernel<<<64, 256, SGEN_SMEM>>>(w1f2w, w1f2b, w2f2w, w2f2b);
    mixpre_mma<<<dim3(16, 64), 256, MIX_SMEM>>>();
    ln_mix_kernel<<<BB * LL, 128>>>(lnmg, lnmb, c1g, c1b);
    bneck_glu_mma<<<dim3(8, 128), 256>>>(bw, bb);
    dwconv_kernel<<<dim3(8, 16, 8), 256>>>(dww, dwb);
    ln2_gelu_kernel<<<BB * LL, 128>>>(c2g, c2b);
    linear_res_mma<<<dim3(4, 128), 256, LIN_SMEM>>>(lw, lb, out);
}

// round 12
// speedup vs baseline: 1.0546x; 1.0546x over previous
#include <cuda_runtime.h>
#include <math.h>
#include <stdint.h>

#define BB 8
#define LL 2048
#define DD 512
#define MM 8
#define DHH 64
#define KHH 256

// ---------------- scratch (device globals; no allocations) ----------------
__device__ float g_H1[64 * 2048 * 64];
__device__ float g_H2[64 * 2048 * 64];
__device__ float g_T1p[4 * 64 * 64 * 64];
__device__ float g_T2[64 * 64 * 64];
__device__ float g_sb[64 * 64];
__device__ float g_mixpre[BB * LL * DD];
__device__ float g_mix[BB * LL * DD];
__device__ float g_u[BB * LL * DD];
__device__ float g_c0[BB * LL * DD];
__device__ float g_v[BB * LL * DD];
__device__ float g_w[BB * LL * DD];

__device__ __forceinline__ float geluf(float x) {
    return 0.5f * x * (1.0f + erff(x * 0.7071067811865476f));
}
__device__ __forceinline__ float sigmoidf_(float x) {
    return 1.0f / (1.0f + expf(-x));
}
__device__ __forceinline__ float pe_val(int l, int c) {
    float ang = (float)l * expf(-(float)(c & ~1) * 0.0179889460390160f);
    return (c & 1) ? cosf(ang) : sinf(ang);
}
__device__ __forceinline__ float tf32r(float x) {
    uint32_t r;
    asm("cvt.rna.tf32.f32 %0, %1;" : "=r"(r) : "f"(x));
    return __uint_as_float(r);
}
__device__ __forceinline__ void split3(float v, uint32_t& hi, uint32_t& lo) {
    uint32_t h;
    asm("cvt.rna.tf32.f32 %0, %1;" : "=r"(h) : "f"(v));
    float r = v - __uint_as_float(h);
    uint32_t l;
    asm("cvt.rna.tf32.f32 %0, %1;" : "=r"(l) : "f"(r));
    hi = h; lo = l;
}
__device__ __forceinline__ void split3f(float v, float& hi, float& lo) {
    uint32_t h, l;
    split3(v, h, l);
    hi = __uint_as_float(h); lo = __uint_as_float(l);
}
__device__ __forceinline__ void mma_tf32(float* c, const uint32_t* a, const uint32_t* b)
{
    asm volatile(
        "mma.sync.aligned.m16n8k8.row.col.f32.tf32.tf32.f32 "
        "{%0,%1,%2,%3}, {%4,%5,%6,%7}, {%8,%9}, {%0,%1,%2,%3};\n"
        : "+f"(c[0]), "+f"(c[1]), "+f"(c[2]), "+f"(c[3])
        : "r"(a[0]), "r"(a[1]), "r"(a[2]), "r"(a[3]), "r"(b[0]), "r"(b[1]));
}

// ============ kernel A: H1,H2 = gelu(fc1_{1,2}(x + pe)) — 3xTF32 mma ============
__global__ void __launch_bounds__(256)
fc1_mma(const float* __restrict__ x,
        const float* __restrict__ f1w_1, const float* __restrict__ f1b_1,
        const float* __restrict__ f1w_2, const float* __restrict__ f1b_2)
{
    extern __shared__ float sm[];
    float* Xs  = sm;                 // [128][68]
    float* W1s = Xs + 128 * 68;      // [64][68]  [h][f]
    float* W2s = W1s + 64 * 68;      // [64][68]
    float* Cs  = W2s + 64 * 68;      // [64][68]
    float* b1s = Cs + 64 * 68;       // 64
    float* b2s = b1s + 64;           // 64
    int tid = threadIdx.x;
    int l0 = blockIdx.x * 128;
    int bm = blockIdx.y;
    int b = bm >> 3, m = bm & 7;

    {
        int f4 = (tid & 15) * 4, r = tid >> 4;
#pragma unroll
        for (int it = 0; it < 8; it++) {
            int row = r + it * 16;
            int l = l0 + row;
            float4 v = *(const float4*)&x[(size_t)(b * LL + l) * DD + m * 64 + f4];
            Xs[row * 68 + f4 + 0] = v.x + pe_val(l, m * 64 + f4 + 0);
            Xs[row * 68 + f4 + 1] = v.y + pe_val(l, m * 64 + f4 + 1);
            Xs[row * 68 + f4 + 2] = v.z + pe_val(l, m * 64 + f4 + 2);
            Xs[row * 68 + f4 + 3] = v.w + pe_val(l, m * 64 + f4 + 3);
        }
#pragma unroll
        for (int it = 0; it < 4; it++) {
            int hh = r + it * 16;
            *(float4*)&W1s[hh * 68 + f4] = *(const float4*)&f1w_1[m * 4096 + hh * 64 + f4];
            *(float4*)&W2s[hh * 68 + f4] = *(const float4*)&f1w_2[m * 4096 + hh * 64 + f4];
        }
        if (tid < 64) { b1s[tid] = f1b_1[m * 64 + tid]; b2s[tid] = f1b_2[m * 64 + tid]; }
    }
    __syncthreads();

    int warp = tid >> 5, lane = tid & 31, gid = lane >> 2, tig = lane & 3;
    int mw = warp & 3, nw = warp >> 2;
    int rb = mw * 32, vb = nw * 32;

    for (int which = 0; which < 2; which++) {
        const float* Ws = which ? W2s : W1s;
        const float* bs = which ? b2s : b1s;
        float* H = which ? g_H2 : g_H1;
        float acc[2][4][4] = {};
#pragma unroll
        for (int kk = 0; kk < 64; kk += 8) {
            uint32_t ah[2][4], al[2][4];
#pragma unroll
            for (int mi = 0; mi < 2; mi++) {
                int rr = rb + mi * 16;
                split3(Xs[(rr + gid) * 68 + kk + tig],     ah[mi][0], al[mi][0]);
                split3(Xs[(rr + gid + 8) * 68 + kk + tig], ah[mi][1], al[mi][1]);
                split3(Xs[(rr + gid) * 68 + kk + tig + 4],     ah[mi][2], al[mi][2]);
                split3(Xs[(rr + gid + 8) * 68 + kk + tig + 4], ah[mi][3], al[mi][3]);
            }
            uint32_t bh[4][2], bl[4][2];
#pragma unroll
            for (int ni = 0; ni < 4; ni++) {
                int cc = vb + ni * 8 + gid;
                split3(Ws[cc * 68 + kk + tig],     bh[ni][0], bl[ni][0]);
                split3(Ws[cc * 68 + kk + tig + 4], bh[ni][1], bl[ni][1]);
            }
#pragma unroll
            for (int mi = 0; mi < 2; mi++)
#pragma unroll
                for (int ni = 0; ni < 4; ni++) {
                    mma_tf32(acc[mi][ni], ah[mi], bh[ni]);
                    mma_tf32(acc[mi][ni], ah[mi], bl[ni]);
                    mma_tf32(acc[mi][ni], al[mi], bh[ni]);
                }
        }
#pragma unroll
        for (int p = 0; p < 2; p++) {
            if ((mw >> 1) == p) {
                int lr = (mw & 1) * 32;
#pragma unroll
                for (int mi = 0; mi < 2; mi++)
#pragma unroll
                    for (int ni = 0; ni < 4; ni++) {
                        int rr = lr + mi * 16 + gid;
                        int cc = vb + ni * 8 + tig * 2;
                        Cs[rr * 68 + cc]           = geluf(acc[mi][ni][0] + bs[cc]);
                        Cs[rr * 68 + cc + 1]       = geluf(acc[mi][ni][1] + bs[cc + 1]);
                        Cs[(rr + 8) * 68 + cc]     = geluf(acc[mi][ni][2] + bs[cc]);
                        Cs[(rr + 8) * 68 + cc + 1] = geluf(acc[mi][ni][3] + bs[cc + 1]);
                    }
            }
            __syncthreads();
#pragma unroll
            for (int it = 0; it < 4; it++) {
                int idx = tid + 256 * it;
                int row = idx >> 4, c4 = (idx & 15) * 4;
                *(float4*)&H[((size_t)bm * LL + l0 + p * 64 + row) * 64 + c4] =
                    *(float4*)&Cs[row * 68 + c4];
            }
            __syncthreads();
        }
    }
}

// ============ kernel B: T1 partial = X_head^T @ H1 — 3xTF32 mma, double-buffered ============
// grid (4 ks, 64 bm); out [64d x 64h], K=512 per block
__global__ void __launch_bounds__(256)
t1_mma(const float* __restrict__ x)
{
    __shared__ float As[2][32][68];   // [buf][kl][d]
    __shared__ float Bs[2][32][68];   // [buf][kl][h]
    int tid = threadIdx.x;
    int ks = blockIdx.x, bm = blockIdx.y;
    int b = bm >> 3, m = bm & 7;
    int warp = tid >> 5, lane = tid & 31, gid = lane >> 2, tig = lane & 3;
    int rb = (warp & 3) * 16, vb = (warp >> 2) * 32;
    float acc[4][4] = {};

    int kl0 = tid >> 4,          d40 = (tid & 15) * 4;
    int kl1 = (tid + 256) >> 4,  d41 = (tid & 15) * 4;
    int lb0 = ks * 512;

    float4 xa0, xa1, hb0, hb1;
    xa0 = *(const float4*)&x[(size_t)(b * LL + lb0 + kl0) * DD + m * 64 + d40];
    xa1 = *(const float4*)&x[(size_t)(b * LL + lb0 + kl1) * DD + m * 64 + d41];
    hb0 = *(const float4*)&g_H1[((size_t)bm * LL + lb0 + kl0) * 64 + d40];
    hb1 = *(const float4*)&g_H1[((size_t)bm * LL + lb0 + kl1) * 64 + d41];
    *(float4*)&As[0][kl0][d40] = xa0;
    *(float4*)&As[0][kl1][d41] = xa1;
    *(float4*)&Bs[0][kl0][d40] = hb0;
    *(float4*)&Bs[0][kl1][d41] = hb1;
    __syncthreads();

    for (int t = 0; t < 16; t++) {
        int cur = t & 1;
        if (t < 15) {
            int lb = ks * 512 + (t + 1) * 32;
            xa0 = *(const float4*)&x[(size_t)(b * LL + lb + kl0) * DD + m * 64 + d40];
            xa1 = *(const float4*)&x[(size_t)(b * LL + lb + kl1) * DD + m * 64 + d41];
            hb0 = *(const float4*)&g_H1[((size_t)bm * LL + lb + kl0) * 64 + d40];
            hb1 = *(const float4*)&g_H1[((size_t)bm * LL + lb + kl1) * 64 + d41];
        }
#pragma unroll
        for (int kk = 0; kk < 32; kk += 8) {
            uint32_t ah[4], al[4];
            split3(As[cur][kk + tig][rb + gid],         ah[0], al[0]);
            split3(As[cur][kk + tig][rb + gid + 8],     ah[1], al[1]);
            split3(As[cur][kk + tig + 4][rb + gid],     ah[2], al[2]);
            split3(As[cur][kk + tig + 4][rb + gid + 8], ah[3], al[3]);
            uint32_t bh[4][2], bl[4][2];
#pragma unroll
            for (int ni = 0; ni < 4; ni++) {
                int cc = vb + ni * 8 + gid;
                split3(Bs[cur][kk + tig][cc],     bh[ni][0], bl[ni][0]);
                split3(Bs[cur][kk + tig + 4][cc], bh[ni][1], bl[ni][1]);
            }
#pragma unroll
            for (int ni = 0; ni < 4; ni++) {
                mma_tf32(acc[ni], ah, bh[ni]);
                mma_tf32(acc[ni], ah, bl[ni]);
                mma_tf32(acc[ni], al, bh[ni]);
            }
        }
        if (t < 15) {
            *(float4*)&As[cur ^ 1][kl0][d40] = xa0;
            *(float4*)&As[cur ^ 1][kl1][d41] = xa1;
            *(float4*)&Bs[cur ^ 1][kl0][d40] = hb0;
            *(float4*)&Bs[cur ^ 1][kl1][d41] = hb1;
        }
        __syncthreads();
    }
    size_t base = ((size_t)(ks * 64 + bm)) * 4096;
#pragma unroll
    for (int ni = 0; ni < 4; ni++) {
        int d0 = rb + gid, h = vb + ni * 8 + tig * 2;
        float2 v0 = {acc[ni][0], acc[ni][1]};
        float2 v1 = {acc[ni][2], acc[ni][3]};
        *(float2*)&g_T1p[base + (size_t)d0 * 64 + h] = v0;
        *(float2*)&g_T1p[base + (size_t)(d0 + 8) * 64 + h] = v1;
    }
}

// ============ kernel C: T1 reduce; S = gelu(...); T2 = S fc2_2; sb = S.b2_2 ============
__global__ void __launch_bounds__(256)
sgen_kernel(const float* __restrict__ x,
            const float* __restrict__ f2w1, const float* __restrict__ f2b1,
            const float* __restrict__ f2w2, const float* __restrict__ f2b2)
{
    extern __shared__ float sm[];
    float* T1s  = sm;
    float* F1s  = T1s + 4160;
    float* F2s  = F1s + 4160;
    float* Ss   = F2s + 4160;
    float* xp   = Ss + 4160;
    float* xsums= xp + 256;
    float* b1s  = xsums + 64;
    float* b2s  = b1s + 64;
    int tid = threadIdx.x;
    int bm = blockIdx.x;
    int b = bm >> 3, m = bm & 7;

#pragma unroll
    for (int r = 0; r < 16; r++) {
        int o = tid + 256 * r;
        float s = 0.f;
#pragma unroll
        for (int ks = 0; ks < 4; ks++)
            s += g_T1p[((size_t)(ks * 64 + bm)) * 4096 + o];
        T1s[(o >> 6) * 65 + (o & 63)] = s;
    }
    {
        int d = tid & 63, p = tid >> 6;
        const float* xp0 = &x[(size_t)(b * LL + p * 512) * DD + m * 64 + d];
        float s = 0.f;
        for (int l = 0; l < 512; l++) s += xp0[(size_t)l * DD];
        xp[p * 64 + d] = s;
    }
    __syncthreads();
    if (tid < 64) xsums[tid] = xp[tid] + xp[64 + tid] + xp[128 + tid] + xp[192 + tid];

    int tx = tid & 15, ty = tid >> 4;
    float t2acc[4][4] = {};
    float sbacc[4] = {};
    for (int c = 0; c < 4; c++) {
        __syncthreads();
#pragma unroll
        for (int r = 0; r < 16; r++) {
            int i = tid + 256 * r;
            int khl = i >> 6, h = i & 63;
            F1s[khl * 65 + h] = f2w1[(size_t)m * 16384 + (c * 64 + khl) * 64 + h];
            F2s[khl * 65 + h] = f2w2[(size_t)m * 16384 + (c * 64 + khl) * 64 + h];
        }
        if (tid < 64) {
            b1s[tid] = f2b1[m * 256 + c * 64 + tid];
            b2s[tid] = f2b2[m * 256 + c * 64 + tid];
        }
        __syncthreads();
        float spre[4][4] = {};
#pragma unroll 8
        for (int h = 0; h < 64; h++) {
            float tv[4], fv[4];
#pragma unroll
            for (int ii = 0; ii < 4; ii++) tv[ii] = T1s[(ty * 4 + ii) * 65 + h];
#pragma unroll
            for (int jj = 0; jj < 4; jj++) fv[jj] = F1s[(tx * 4 + jj) * 65 + h];
#pragma unroll
            for (int ii = 0; ii < 4; ii++)
#pragma unroll
                for (int jj = 0; jj < 4; jj++)
                    spre[ii][jj] += tv[ii] * fv[jj];
        }
#pragma unroll
        for (int ii = 0; ii < 4; ii++)
#pragma unroll
            for (int jj = 0; jj < 4; jj++) {
                int d = ty * 4 + ii, khl = tx * 4 + jj;
                Ss[d * 65 + khl] = geluf(spre[ii][jj] + xsums[d] * b1s[khl]);
            }
        __syncthreads();
#pragma unroll 8
        for (int khl = 0; khl < 64; khl++) {
            float sv[4], fv[4];
#pragma unroll
            for (int ii = 0; ii < 4; ii++) sv[ii] = Ss[(ty * 4 + ii) * 65 + khl];
#pragma unroll
            for (int jj = 0; jj < 4; jj++) fv[jj] = F2s[khl * 65 + tx * 4 + jj];
#pragma unroll
            for (int ii = 0; ii < 4; ii++)
#pragma unroll
                for (int jj = 0; jj < 4; jj++)
                    t2acc[ii][jj] += sv[ii] * fv[jj];
            if (tx == 0) {
                float bv = b2s[khl];
#pragma unroll
                for (int ii = 0; ii < 4; ii++) sbacc[ii] += sv[ii] * bv;
            }
        }
    }
#pragma unroll
    for (int ii = 0; ii < 4; ii++)
#pragma unroll
        for (int jj = 0; jj < 4; jj++)
            g_T2[(size_t)bm * 4096 + (ty * 4 + ii) * 64 + tx * 4 + jj] = t2acc[ii][jj];
    if (tx == 0)
#pragma unroll
        for (int ii = 0; ii < 4; ii++) g_sb[bm * 64 + ty * 4 + ii] = sbacc[ii];
}

// ============ kernel E: mixpre = H2 @ T2^T + sb — 3xTF32, hi/lo hoisted ============
__global__ void __launch_bounds__(256)
mixpre_mma()
{
    extern __shared__ float sm[];
    float* Hh  = sm;                // [128][68]
    float* Hl  = Hh + 128 * 68;     // [128][68]
    float* Th  = Hl + 128 * 68;     // [64][68]  (reused as Cs in epilogue)
    float* Tl  = Th + 64 * 68;      // [64][68]
    float* sbs = Tl + 64 * 68;      // 64
    float* Cs  = Th;
    int tid = threadIdx.x;
    int l0 = blockIdx.x * 128;
    int bm = blockIdx.y;
    int b = bm >> 3, m = bm & 7;

    {
        int f4 = (tid & 15) * 4, r = tid >> 4;
#pragma unroll
        for (int it = 0; it < 8; it++) {
            int row = r + it * 16;
            float4 v = *(const float4*)&g_H2[((size_t)bm * LL + l0 + row) * 64 + f4];
            split3f(v.x, Hh[row * 68 + f4 + 0], Hl[row * 68 + f4 + 0]);
            split3f(v.y, Hh[row * 68 + f4 + 1], Hl[row * 68 + f4 + 1]);
            split3f(v.z, Hh[row * 68 + f4 + 2], Hl[row * 68 + f4 + 2]);
            split3f(v.w, Hh[row * 68 + f4 + 3], Hl[row * 68 + f4 + 3]);
        }
#pragma unroll
        for (int it = 0; it < 4; it++) {
            int dd = r + it * 16;
            float4 v = *(const float4*)&g_T2[(size_t)bm * 4096 + dd * 64 + f4];
            split3f(v.x, Th[dd * 68 + f4 + 0], Tl[dd * 68 + f4 + 0]);
            split3f(v.y, Th[dd * 68 + f4 + 1], Tl[dd * 68 + f4 + 1]);
            split3f(v.z, Th[dd * 68 + f4 + 2], Tl[dd * 68 + f4 + 2]);
            split3f(v.w, Th[dd * 68 + f4 + 3], Tl[dd * 68 + f4 + 3]);
        }
        if (tid < 64) sbs[tid] = g_sb[bm * 64 + tid];
    }
    __syncthreads();

    int warp = tid >> 5, lane = tid & 31, gid = lane >> 2, tig = lane & 3;
    int mw = warp & 3, nw = warp >> 2;
    int rb = mw * 32, vb = nw * 32;

    float acc[2][4][4] = {};
#pragma unroll
    for (int kk = 0; kk < 64; kk += 8) {
        uint32_t ah[2][4], al[2][4];
#pragma unroll
        for (int mi = 0; mi < 2; mi++) {
            int rr = rb + mi * 16;
            ah[mi][0] = __float_as_uint(Hh[(rr + gid) * 68 + kk + tig]);
            al[mi][0] = __float_as_uint(Hl[(rr + gid) * 68 + kk + tig]);
            ah[mi][1] = __float_as_uint(Hh[(rr + gid + 8) * 68 + kk + tig]);
            al[mi][1] = __float_as_uint(Hl[(rr + gid + 8) * 68 + kk + tig]);
            ah[mi][2] = __float_as_uint(Hh[(rr + gid) * 68 + kk + tig + 4]);
            al[mi][2] = __float_as_uint(Hl[(rr + gid) * 68 + kk + tig + 4]);
            ah[mi][3] = __float_as_uint(Hh[(rr + gid + 8) * 68 + kk + tig + 4]);
            al[mi][3] = __float_as_uint(Hl[(rr + gid + 8) * 68 + kk + tig + 4]);
        }
        uint32_t bh[4][2], bl[4][2];
#pragma unroll
        for (int ni = 0; ni < 4; ni++) {
            int cc = vb + ni * 8 + gid;
            bh[ni][0] = __float_as_uint(Th[cc * 68 + kk + tig]);
            bl[ni][0] = __float_as_uint(Tl[cc * 68 + kk + tig]);
            bh[ni][1] = __float_as_uint(Th[cc * 68 + kk + tig + 4]);
            bl[ni][1] = __float_as_uint(Tl[cc * 68 + kk + tig + 4]);
        }
#pragma unroll
        for (int mi = 0; mi < 2; mi++)
#pragma unroll
            for (int ni = 0; ni < 4; ni++) {
                mma_tf32(acc[mi][ni], ah[mi], bh[ni]);
                mma_tf32(acc[mi][ni], ah[mi], bl[ni]);
                mma_tf32(acc[mi][ni], al[mi], bh[ni]);
            }
    }
    __syncthreads();   // tile reads done before Cs overlays Th
#pragma unroll
    for (int p = 0; p < 2; p++) {
        if ((mw >> 1) == p) {
            int lr = (mw & 1) * 32;
#pragma unroll
            for (int mi = 0; mi < 2; mi++)
#pragma unroll
                for (int ni = 0; ni < 4; ni++) {
                    int rr = lr + mi * 16 + gid;
                    int cc = vb + ni * 8 + tig * 2;
                    Cs[rr * 68 + cc]           = acc[mi][ni][0] + sbs[cc];
                    Cs[rr * 68 + cc + 1]       = acc[mi][ni][1] + sbs[cc + 1];
                    Cs[(rr + 8) * 68 + cc]     = acc[mi][ni][2] + sbs[cc];
                    Cs[(rr + 8) * 68 + cc + 1] = acc[mi][ni][3] + sbs[cc + 1];
                }
        }
        __syncthreads();
#pragma unroll
        for (int it = 0; it < 4; it++) {
            int idx = tid + 256 * it;
            int row = idx >> 4, c4 = (idx & 15) * 4;
            *(float4*)&g_mixpre[(size_t)(b * LL + l0 + p * 64 + row) * DD + m * 64 + c4] =
                *(float4*)&Cs[row * 68 + c4];
        }
        __syncthreads();
    }
}

// ---------------- LN helpers ----------------
__device__ __forceinline__ float blk_sum128(float v, float* sbuf)
{
#pragma unroll
    for (int o = 16; o; o >>= 1) v += __shfl_xor_sync(0xffffffffu, v, o);
    __syncthreads();
    if ((threadIdx.x & 31) == 0) sbuf[threadIdx.x >> 5] = v;
    __syncthreads();
    return sbuf[0] + sbuf[1] + sbuf[2] + sbuf[3];
}

__global__ void __launch_bounds__(128)
ln_mix_kernel(const float* __restrict__ g1, const float* __restrict__ b1,
              const float* __restrict__ g2, const float* __restrict__ b2)
{
    __shared__ float sbuf[4];
    size_t row = blockIdx.x;
    int t = threadIdx.x;
    const float* r = g_mixpre + row * DD;
    float v[4];
#pragma unroll
    for (int i = 0; i < 4; i++) v[i] = r[t + 128 * i];
    float mean = blk_sum128(v[0] + v[1] + v[2] + v[3], sbuf) * (1.0f / 512.0f);
    float sq = 0.f;
#pragma unroll
    for (int i = 0; i < 4; i++) { float d = v[i] - mean; sq += d * d; }
    float var = blk_sum128(sq, sbuf) * (1.0f / 512.0f);
    float inv = rsqrtf(var + 1e-5f);
    float mx[4];
#pragma unroll
    for (int i = 0; i < 4; i++) {
        int c = t + 128 * i;
        mx[i] = (v[i] - mean) * inv * g1[c] + b1[c];
        g_mix[row * DD + c] = mx[i];
    }
    float mean2 = blk_sum128(mx[0] + mx[1] + mx[2] + mx[3], sbuf) * (1.0f / 512.0f);
    float sq2 = 0.f;
#pragma unroll
    for (int i = 0; i < 4; i++) { float d = mx[i] - mean2; sq2 += d * d; }
    float var2 = blk_sum128(sq2, sbuf) * (1.0f / 512.0f);
    float inv2 = rsqrtf(var2 + 1e-5f);
#pragma unroll
    for (int i = 0; i < 4; i++) {
        int c = t + 128 * i;
        g_u[row * DD + c] = (mx[i] - mean2) * inv2 * g2[c] + b2[c];
    }
}

// ============ bottleneck 1x1 + GLU via tf32 mma — double-buffered ============
__global__ void __launch_bounds__(256)
bneck_glu_mma(const float* __restrict__ bw, const float* __restrict__ bb)
{
    __shared__ float As[2][16][132];
    __shared__ float Bs[2][16][132];
    __shared__ float Cs[32][68];
    int tid = threadIdx.x;
    int warp = tid >> 5, lane = tid & 31;
    int mw = warp & 3, nw = warp >> 2;
    int gid = lane >> 2, tig = lane & 3;
    int r0 = blockIdx.y * 128, n0 = blockIdx.x * 64;

    float acc[2][8][4] = {};

    int arow = tid >> 1;
    int akq  = (tid & 1) * 8;
    int vcol = tid >> 1;
    int brr  = (vcol & 1) ? (512 + n0 + (vcol >> 1)) : (n0 + (vcol >> 1));

    const float* pA = &g_u[(size_t)(r0 + arow) * 512 + akq];
    const float* pB = &bw[(size_t)brr * 512 + akq];

    float ar[8], br[8];
    *(float4*)&ar[0] = *(const float4*)pA;
    *(float4*)&ar[4] = *(const float4*)(pA + 4);
    *(float4*)&br[0] = *(const float4*)pB;
    *(float4*)&br[4] = *(const float4*)(pB + 4);
#pragma unroll
    for (int j = 0; j < 8; j++) {
        As[0][akq + j][arow] = tf32r(ar[j]);
        Bs[0][akq + j][vcol] = tf32r(br[j]);
    }
    __syncthreads();

    for (int t = 0; t < 32; t++) {
        int cur = t & 1;
        if (t < 31) {
            const float* qA = pA + (t + 1) * 16;
            const float* qB = pB + (t + 1) * 16;
            *(float4*)&ar[0] = *(const float4*)qA;
            *(float4*)&ar[4] = *(const float4*)(qA + 4);
            *(float4*)&br[0] = *(const float4*)qB;
            *(float4*)&br[4] = *(const float4*)(qB + 4);
        }
#pragma unroll
        for (int kk = 0; kk < 16; kk += 8) {
            uint32_t a[2][4];
#pragma unroll
            for (int mi = 0; mi < 2; mi++) {
                int rb = mw * 32 + mi * 16;
                a[mi][0] = __float_as_uint(As[cur][kk + tig][rb + gid]);
                a[mi][1] = __float_as_uint(As[cur][kk + tig][rb + gid + 8]);
                a[mi][2] = __float_as_uint(As[cur][kk + tig + 4][rb + gid]);
                a[mi][3] = __float_as_uint(As[cur][kk + tig + 4][rb + gid + 8]);
            }
            uint32_t bfr[8][2];
#pragma unroll
            for (int ni = 0; ni < 8; ni++) {
                int vb = nw * 64 + ni * 8;
                bfr[ni][0] = __float_as_uint(Bs[cur][kk + tig][vb + gid]);
                bfr[ni][1] = __float_as_uint(Bs[cur][kk + tig + 4][vb + gid]);
            }
#pragma unroll
            for (int mi = 0; mi < 2; mi++)
#pragma unroll
                for (int ni = 0; ni < 8; ni++)
                    mma_tf32(acc[mi][ni], a[mi], bfr[ni]);
        }
        if (t < 31) {
#pragma unroll
            for (int j = 0; j < 8; j++) {
                As[cur ^ 1][akq + j][arow] = tf32r(ar[j]);
                Bs[cur ^ 1][akq + j][vcol] = tf32r(br[j]);
            }
        }
        __syncthreads();
    }

    float bbA[8], bbB[8];
#pragma unroll
    for (int ni = 0; ni < 8; ni++) {
        int cR = n0 + nw * 32 + ni * 4 + tig;
        bbA[ni] = bb[cR];
        bbB[ni] = bb[512 + cR];
    }
    for (int p = 0; p < 4; p++) {
        if (mw == p) {
#pragma unroll
            for (int mi = 0; mi < 2; mi++)
#pragma unroll
                for (int ni = 0; ni < 8; ni++) {
                    int cc = nw * 32 + ni * 4 + tig;
                    float ga0 = acc[mi][ni][0] + bbA[ni];
                    float gb0 = acc[mi][ni][1] + bbB[ni];
                    float ga1 = acc[mi][ni][2] + bbA[ni];
                    float gb1 = acc[mi][ni][3] + bbB[ni];
                    Cs[mi * 16 + gid][cc]     = ga0 * sigmoidf_(gb0);
                    Cs[mi * 16 + gid + 8][cc] = ga1 * sigmoidf_(gb1);
                }
        }
        __syncthreads();
        {
            int row = tid >> 3, c = (tid & 7) * 8;
            float4 v0 = *(float4*)&Cs[row][c];
            float4 v1 = *(float4*)&Cs[row][c + 4];
            float* op = &g_c0[(size_t)(r0 + p * 32 + row) * 512 + n0 + c];
            *(float4*)op = v0;
            *(float4*)(op + 4) = v1;
        }
        __syncthreads();
    }
}

// ============ depthwise conv (K=31, pad 15) — register sliding window ============
__global__ void __launch_bounds__(256)
dwconv_kernel(const float* __restrict__ dw, const float* __restrict__ dwb)
{
    __shared__ float ins[158 * 64];
    __shared__ float wts[64 * 31];
    __shared__ float bs[64];
    int tid = threadIdx.x;
    int c0 = blockIdx.x * 64;
    int l0 = blockIdx.y * 128;
    int b  = blockIdx.z;
    for (int i = tid; i < 158 * 64; i += 256) {
        int rr = i >> 6, c = i & 63;
        int l = l0 - 15 + rr;
        ins[i] = (l >= 0 && l < LL) ? g_c0[((size_t)(b * LL + l)) * DD + c0 + c] : 0.f;
    }
    for (int i = tid; i < 64 * 31; i += 256)
        wts[i] = dw[c0 * 31 + i];
    if (tid < 64) bs[tid] = dwb[c0 + tid];
    __syncthreads();
    int tx = tid & 63, ty = tid >> 6;
    float w[31];
#pragma unroll
    for (int j = 0; j < 31; j++) w[j] = wts[tx * 31 + j];
    float bias = bs[tx];
    int base = ty * 32;
    float win[31];
#pragma unroll
    for (int j = 0; j < 30; j++) win[j] = ins[(base + j) * 64 + tx];
#pragma unroll
    for (int li = 0; li < 32; li++) {
        win[30] = ins[(base + li + 30) * 64 + tx];
        float acc = bias;
#pragma unroll
        for (int j = 0; j < 31; j++) acc += win[j] * w[j];
        g_v[((size_t)(b * LL + l0 + base + li)) * DD + c0 + tx] = acc;
#pragma unroll
        for (int j = 0; j < 30; j++) win[j] = win[j + 1];
    }
}

// ============ LN2 + gelu ============
__global__ void __launch_bounds__(128)
ln2_gelu_kernel(const float* __restrict__ g2, const float* __restrict__ b2)
{
    __shared__ float sbuf[4];
    size_t row = blockIdx.x;
    int t = threadIdx.x;
    const float* r = g_v + row * DD;
    float v[4];
#pragma unroll
    for (int i = 0; i < 4; i++) v[i] = r[t + 128 * i];
    float mean = blk_sum128(v[0] + v[1] + v[2] + v[3], sbuf) * (1.0f / 512.0f);
    float sq = 0.f;
#pragma unroll
    for (int i = 0; i < 4; i++) { float d = v[i] - mean; sq += d * d; }
    float var = blk_sum128(sq, sbuf) * (1.0f / 512.0f);
    float inv = rsqrtf(var + 1e-5f);
#pragma unroll
    for (int i = 0; i < 4; i++) {
        int c = t + 128 * i;
        g_w[row * DD + c] = geluf((v[i] - mean) * inv * g2[c] + b2[c]);
    }
}

// ============ final linear + bias + residual via tf32 mma — double-buffered ============
__global__ void __launch_bounds__(256)
linear_res_mma(const float* __restrict__ lw, const float* __restrict__ lb,
               float* __restrict__ out)
{
    extern __shared__ float smd[];
    float* Asd = smd;
    float* Bsd = smd + 4224;
    float* Csd = smd + 8448;
#define LAS(bf, k, r) Asd[(bf) * 2112 + (k) * 132 + (r)]
#define LBS(bf, k, r) Bsd[(bf) * 2112 + (k) * 132 + (r)]
    int tid = threadIdx.x;
    int warp = tid >> 5, lane = tid & 31;
    int mw = warp & 3, nw = warp >> 2;
    int gid = lane >> 2, tig = lane & 3;
    int r0 = blockIdx.y * 128, n0 = blockIdx.x * 128;

    float acc[2][8][4] = {};

    int arow = tid >> 1;
    int akq  = (tid & 1) * 8;

    const float* pA = &g_w[(size_t)(r0 + arow) * 512 + akq];
    const float* pB = &lw[(size_t)(n0 + arow) * 512 + akq];

    float ar[8], br[8];
    *(float4*)&ar[0] = *(const float4*)pA;
    *(float4*)&ar[4] = *(const float4*)(pA + 4);
    *(float4*)&br[0] = *(const float4*)pB;
    *(float4*)&br[4] = *(const float4*)(pB + 4);
#pragma unroll
    for (int j = 0; j < 8; j++) {
        LAS(0, akq + j, arow) = tf32r(ar[j]);
        LBS(0, akq + j, arow) = tf32r(br[j]);
    }
    __syncthreads();

    for (int t = 0; t < 32; t++) {
        int cur = t & 1;
        if (t < 31) {
            const float* qA = pA + (t + 1) * 16;
            const float* qB = pB + (t + 1) * 16;
            *(float4*)&ar[0] = *(const float4*)qA;
            *(float4*)&ar[4] = *(const float4*)(qA + 4);
            *(float4*)&br[0] = *(const float4*)qB;
            *(float4*)&br[4] = *(const float4*)(qB + 4);
        }
#pragma unroll
        for (int kk = 0; kk < 16; kk += 8) {
            uint32_t a[2][4];
#pragma unroll
            for (int mi = 0; mi < 2; mi++) {
                int rb = mw * 32 + mi * 16;
                a[mi][0] = __float_as_uint(LAS(cur, kk + tig, rb + gid));
                a[mi][1] = __float_as_uint(LAS(cur, kk + tig, rb + gid + 8));
                a[mi][2] = __float_as_uint(LAS(cur, kk + tig + 4, rb + gid));
                a[mi][3] = __float_as_uint(LAS(cur, kk + tig + 4, rb + gid + 8));
            }
            uint32_t bfr[8][2];
#pragma unroll
            for (int ni = 0; ni < 8; ni++) {
                int vb = nw * 64 + ni * 8;
                bfr[ni][0] = __float_as_uint(LBS(cur, kk + tig, vb + gid));
                bfr[ni][1] = __float_as_uint(LBS(cur, kk + tig + 4, vb + gid));
            }
#pragma unroll
            for (int mi = 0; mi < 2; mi++)
#pragma unroll
                for (int ni = 0; ni < 8; ni++)
                    mma_tf32(acc[mi][ni], a[mi], bfr[ni]);
        }
        if (t < 31) {
#pragma unroll
            for (int j = 0; j < 8; j++) {
                LAS(cur ^ 1, akq + j, arow) = tf32r(ar[j]);
                LBS(cur ^ 1, akq + j, arow) = tf32r(br[j]);
            }
        }
        __syncthreads();
    }

    for (int p = 0; p < 4; p++) {
        if (mw == p) {
#pragma unroll
            for (int mi = 0; mi < 2; mi++)
#pragma unroll
                for (int ni = 0; ni < 8; ni++) {
                    int cc = nw * 64 + ni * 8 + tig * 2;
                    Csd[(mi * 16 + gid) * 132 + cc]         = acc[mi][ni][0];
                    Csd[(mi * 16 + gid) * 132 + cc + 1]     = acc[mi][ni][1];
                    Csd[(mi * 16 + gid + 8) * 132 + cc]     = acc[mi][ni][2];
                    Csd[(mi * 16 + gid + 8) * 132 + cc + 1] = acc[mi][ni][3];
                }
        }
        __syncthreads();
        {
            int row = tid >> 3, c0c = (tid & 7) * 16;
            size_t gro = (size_t)(r0 + p * 32 + row) * 512 + n0;
#pragma unroll
            for (int q = 0; q < 4; q++) {
                int c = c0c + q * 4;
                float4 v = *(float4*)&Csd[row * 132 + c];
                float4 mres = *(const float4*)&g_mix[gro + c];
                float4 bl = *(const float4*)&lb[n0 + c];
                v.x += bl.x + mres.x; v.y += bl.y + mres.y;
                v.z += bl.z + mres.z; v.w += bl.w + mres.w;
                *(float4*)&out[gro + c] = v;
            }
        }
        __syncthreads();
    }
#undef LAS
#undef LBS
}

// ---------------- launch ----------------
extern "C" void kernel_launch(void* const* d_in, const int* in_sizes, int n_in,
                              void* d_out, int out_size)
{
    (void)in_sizes; (void)n_in; (void)out_size;
    const float* x      = (const float*)d_in[0];
    const float* w1f1w  = (const float*)d_in[1];
    const float* w1f1b  = (const float*)d_in[2];
    const float* w1f2w  = (const float*)d_in[3];
    const float* w1f2b  = (const float*)d_in[4];
    const float* w2f1w  = (const float*)d_in[5];
    const float* w2f1b  = (const float*)d_in[6];
    const float* w2f2w  = (const float*)d_in[7];
    const float* w2f2b  = (const float*)d_in[8];
    const float* lnmg   = (const float*)d_in[9];
    const float* lnmb   = (const float*)d_in[10];
    const float* c1g    = (const float*)d_in[11];
    const float* c1b    = (const float*)d_in[12];
    const float* bw     = (const float*)d_in[13];
    const float* bb     = (const float*)d_in[14];
    const float* dww    = (const float*)d_in[15];
    const float* dwb    = (const float*)d_in[16];
    const float* c2g    = (const float*)d_in[17];
    const float* c2b    = (const float*)d_in[18];
    const float* lw     = (const float*)d_in[19];
    const float* lb     = (const float*)d_in[20];
    float* out = (float*)d_out;

    const int SGEN_SMEM = (4 * 4160 + 256 + 64 + 64 + 64) * 4;
    const int FC1_SMEM  = (128 * 68 + 64 * 68 * 3 + 128) * 4;      // 87,552 B
    const int MIX_SMEM  = (2 * 128 * 68 + 2 * 64 * 68 + 64) * 4;   // 104,704 B
    const int LIN_SMEM  = (2 * 2112 * 2 + 32 * 132) * 4;           // 50,688 B
    cudaFuncSetAttribute(sgen_kernel, cudaFuncAttributeMaxDynamicSharedMemorySize, SGEN_SMEM);
    cudaFuncSetAttribute(fc1_mma, cudaFuncAttributeMaxDynamicSharedMemorySize, FC1_SMEM);
    cudaFuncSetAttribute(mixpre_mma, cudaFuncAttributeMaxDynamicSharedMemorySize, MIX_SMEM);
    cudaFuncSetAttribute(linear_res_mma, cudaFuncAttributeMaxDynamicSharedMemorySize, LIN_SMEM);

    fc1_mma<<<dim3(16, 64), 256, FC1_SMEM>>>(x, w1f1w, w1f1b, w2f1w, w2f1b);
    t1_mma<<<dim3(4, 64), 256>>>(x);
    sgen_kernel<<<64, 256, SGEN_SMEM>>>(x, w1f2w, w1f2b, w2f2w, w2f2b);
    mixpre_mma<<<dim3(16, 64), 256, MIX_SMEM>>>();
    ln_mix_kernel<<<BB * LL, 128>>>(lnmg, lnmb, c1g, c1b);
    bneck_glu_mma<<<dim3(8, 128), 256>>>(bw, bb);
    dwconv_kernel<<<dim3(8, 16, 8), 256>>>(dww, dwb);
    ln2_gelu_kernel<<<BB * LL, 128>>>(c2g, c2b);
    linear_res_mma<<<dim3(4, 128), 256, LIN_SMEM>>>(lw, lb, out);
}

// round 14
// speedup vs baseline: 1.0845x; 1.0284x over previous
#include <cuda_runtime.h>
#include <math.h>
#include <stdint.h>

#define BB 8
#define LL 2048
#define DD 512
#define MM 8
#define DHH 64
#define KHH 256

// ---------------- scratch (device globals; no allocations) ----------------
__device__ float g_H1[64 * 2048 * 64];
__device__ float g_H2[64 * 2048 * 64];
__device__ float g_T1p[4 * 64 * 64 * 64];
__device__ float g_T2[64 * 64 * 64];
__device__ float g_sb[64 * 64];
__device__ float g_mixpre[BB * LL * DD];
__device__ float g_mix[BB * LL * DD];
__device__ float g_u[BB * LL * DD];
__device__ float g_c0[BB * LL * DD];
__device__ float g_v[BB * LL * DD];
__device__ float g_w[BB * LL * DD];

__device__ __forceinline__ float geluf(float x) {
    return 0.5f * x * (1.0f + erff(x * 0.7071067811865476f));
}
__device__ __forceinline__ float sigmoidf_(float x) {
    return 1.0f / (1.0f + expf(-x));
}
__device__ __forceinline__ float pe_val(int l, int c) {
    float ang = (float)l * expf(-(float)(c & ~1) * 0.0179889460390160f);
    return (c & 1) ? cosf(ang) : sinf(ang);
}
__device__ __forceinline__ float tf32r(float x) {
    uint32_t r;
    asm("cvt.rna.tf32.f32 %0, %1;" : "=r"(r) : "f"(x));
    return __uint_as_float(r);
}
__device__ __forceinline__ void split3(float v, uint32_t& hi, uint32_t& lo) {
    uint32_t h;
    asm("cvt.rna.tf32.f32 %0, %1;" : "=r"(h) : "f"(v));
    float r = v - __uint_as_float(h);
    uint32_t l;
    asm("cvt.rna.tf32.f32 %0, %1;" : "=r"(l) : "f"(r));
    hi = h; lo = l;
}
__device__ __forceinline__ void mma_tf32(float* c, const uint32_t* a, const uint32_t* b)
{
    asm volatile(
        "mma.sync.aligned.m16n8k8.row.col.f32.tf32.tf32.f32 "
        "{%0,%1,%2,%3}, {%4,%5,%6,%7}, {%8,%9}, {%0,%1,%2,%3};\n"
        : "+f"(c[0]), "+f"(c[1]), "+f"(c[2]), "+f"(c[3])
        : "r"(a[0]), "r"(a[1]), "r"(a[2]), "r"(a[3]), "r"(b[0]), "r"(b[1]));
}

// ============ kernel A: H1,H2 = gelu(fc1_{1,2}(x + pe)) — 3xTF32 mma ============
__global__ void __launch_bounds__(256)
fc1_mma(const float* __restrict__ x,
        const float* __restrict__ f1w_1, const float* __restrict__ f1b_1,
        const float* __restrict__ f1w_2, const float* __restrict__ f1b_2)
{
    extern __shared__ float sm[];
    float* Xs  = sm;                 // [128][68]
    float* W1s = Xs + 128 * 68;      // [64][68]  [h][f]
    float* W2s = W1s + 64 * 68;      // [64][68]
    float* Cs  = W2s + 64 * 68;      // [64][68]
    float* b1s = Cs + 64 * 68;       // 64
    float* b2s = b1s + 64;           // 64
    int tid = threadIdx.x;
    int l0 = blockIdx.x * 128;
    int bm = blockIdx.y;
    int b = bm >> 3, m = bm & 7;

    {
        int f4 = (tid & 15) * 4, r = tid >> 4;
#pragma unroll
        for (int it = 0; it < 8; it++) {
            int row = r + it * 16;
            int l = l0 + row;
            float4 v = *(const float4*)&x[(size_t)(b * LL + l) * DD + m * 64 + f4];
            Xs[row * 68 + f4 + 0] = v.x + pe_val(l, m * 64 + f4 + 0);
            Xs[row * 68 + f4 + 1] = v.y + pe_val(l, m * 64 + f4 + 1);
            Xs[row * 68 + f4 + 2] = v.z + pe_val(l, m * 64 + f4 + 2);
            Xs[row * 68 + f4 + 3] = v.w + pe_val(l, m * 64 + f4 + 3);
        }
#pragma unroll
        for (int it = 0; it < 4; it++) {
            int hh = r + it * 16;
            *(float4*)&W1s[hh * 68 + f4] = *(const float4*)&f1w_1[m * 4096 + hh * 64 + f4];
            *(float4*)&W2s[hh * 68 + f4] = *(const float4*)&f1w_2[m * 4096 + hh * 64 + f4];
        }
        if (tid < 64) { b1s[tid] = f1b_1[m * 64 + tid]; b2s[tid] = f1b_2[m * 64 + tid]; }
    }
    __syncthreads();

    int warp = tid >> 5, lane = tid & 31, gid = lane >> 2, tig = lane & 3;
    int mw = warp & 3, nw = warp >> 2;
    int rb = mw * 32, vb = nw * 32;

    for (int which = 0; which < 2; which++) {
        const float* Ws = which ? W2s : W1s;
        const float* bs = which ? b2s : b1s;
        float* H = which ? g_H2 : g_H1;
        float acc[2][4][4] = {};
#pragma unroll
        for (int kk = 0; kk < 64; kk += 8) {
            uint32_t ah[2][4], al[2][4];
#pragma unroll
            for (int mi = 0; mi < 2; mi++) {
                int rr = rb + mi * 16;
                split3(Xs[(rr + gid) * 68 + kk + tig],     ah[mi][0], al[mi][0]);
                split3(Xs[(rr + gid + 8) * 68 + kk + tig], ah[mi][1], al[mi][1]);
                split3(Xs[(rr + gid) * 68 + kk + tig + 4],     ah[mi][2], al[mi][2]);
                split3(Xs[(rr + gid + 8) * 68 + kk + tig + 4], ah[mi][3], al[mi][3]);
            }
            uint32_t bh[4][2], bl[4][2];
#pragma unroll
            for (int ni = 0; ni < 4; ni++) {
                int cc = vb + ni * 8 + gid;
                split3(Ws[cc * 68 + kk + tig],     bh[ni][0], bl[ni][0]);
                split3(Ws[cc * 68 + kk + tig + 4], bh[ni][1], bl[ni][1]);
            }
#pragma unroll
            for (int mi = 0; mi < 2; mi++)
#pragma unroll
                for (int ni = 0; ni < 4; ni++) {
                    mma_tf32(acc[mi][ni], ah[mi], bh[ni]);
                    mma_tf32(acc[mi][ni], ah[mi], bl[ni]);
                    mma_tf32(acc[mi][ni], al[mi], bh[ni]);
                }
        }
#pragma unroll
        for (int p = 0; p < 2; p++) {
            if ((mw >> 1) == p) {
                int lr = (mw & 1) * 32;
#pragma unroll
                for (int mi = 0; mi < 2; mi++)
#pragma unroll
                    for (int ni = 0; ni < 4; ni++) {
                        int rr = lr + mi * 16 + gid;
                        int cc = vb + ni * 8 + tig * 2;
                        Cs[rr * 68 + cc]           = geluf(acc[mi][ni][0] + bs[cc]);
                        Cs[rr * 68 + cc + 1]       = geluf(acc[mi][ni][1] + bs[cc + 1]);
                        Cs[(rr + 8) * 68 + cc]     = geluf(acc[mi][ni][2] + bs[cc]);
                        Cs[(rr + 8) * 68 + cc + 1] = geluf(acc[mi][ni][3] + bs[cc + 1]);
                    }
            }
            __syncthreads();
#pragma unroll
            for (int it = 0; it < 4; it++) {
                int idx = tid + 256 * it;
                int row = idx >> 4, c4 = (idx & 15) * 4;
                *(float4*)&H[((size_t)bm * LL + l0 + p * 64 + row) * 64 + c4] =
                    *(float4*)&Cs[row * 68 + c4];
            }
            __syncthreads();
        }
    }
}

// ============ kernel B: T1 partial = X_head^T @ H1 — 3xTF32 mma, double-buffered ============
__global__ void __launch_bounds__(256)
t1_mma(const float* __restrict__ x)
{
    __shared__ float As[2][32][68];   // [buf][kl][d]
    __shared__ float Bs[2][32][68];   // [buf][kl][h]
    int tid = threadIdx.x;
    int ks = blockIdx.x, bm = blockIdx.y;
    int b = bm >> 3, m = bm & 7;
    int warp = tid >> 5, lane = tid & 31, gid = lane >> 2, tig = lane & 3;
    int rb = (warp & 3) * 16, vb = (warp >> 2) * 32;
    float acc[4][4] = {};

    int kl0 = tid >> 4,          d40 = (tid & 15) * 4;
    int kl1 = (tid + 256) >> 4,  d41 = (tid & 15) * 4;
    int lb0 = ks * 512;

    float4 xa0, xa1, hb0, hb1;
    xa0 = *(const float4*)&x[(size_t)(b * LL + lb0 + kl0) * DD + m * 64 + d40];
    xa1 = *(const float4*)&x[(size_t)(b * LL + lb0 + kl1) * DD + m * 64 + d41];
    hb0 = *(const float4*)&g_H1[((size_t)bm * LL + lb0 + kl0) * 64 + d40];
    hb1 = *(const float4*)&g_H1[((size_t)bm * LL + lb0 + kl1) * 64 + d41];
    *(float4*)&As[0][kl0][d40] = xa0;
    *(float4*)&As[0][kl1][d41] = xa1;
    *(float4*)&Bs[0][kl0][d40] = hb0;
    *(float4*)&Bs[0][kl1][d41] = hb1;
    __syncthreads();

    for (int t = 0; t < 16; t++) {
        int cur = t & 1;
        if (t < 15) {
            int lb = ks * 512 + (t + 1) * 32;
            xa0 = *(const float4*)&x[(size_t)(b * LL + lb + kl0) * DD + m * 64 + d40];
            xa1 = *(const float4*)&x[(size_t)(b * LL + lb + kl1) * DD + m * 64 + d41];
            hb0 = *(const float4*)&g_H1[((size_t)bm * LL + lb + kl0) * 64 + d40];
            hb1 = *(const float4*)&g_H1[((size_t)bm * LL + lb + kl1) * 64 + d41];
        }
#pragma unroll
        for (int kk = 0; kk < 32; kk += 8) {
            uint32_t ah[4], al[4];
            split3(As[cur][kk + tig][rb + gid],         ah[0], al[0]);
            split3(As[cur][kk + tig][rb + gid + 8],     ah[1], al[1]);
            split3(As[cur][kk + tig + 4][rb + gid],     ah[2], al[2]);
            split3(As[cur][kk + tig + 4][rb + gid + 8], ah[3], al[3]);
            uint32_t bh[4][2], bl[4][2];
#pragma unroll
            for (int ni = 0; ni < 4; ni++) {
                int cc = vb + ni * 8 + gid;
                split3(Bs[cur][kk + tig][cc],     bh[ni][0], bl[ni][0]);
                split3(Bs[cur][kk + tig + 4][cc], bh[ni][1], bl[ni][1]);
            }
#pragma unroll
            for (int ni = 0; ni < 4; ni++) {
                mma_tf32(acc[ni], ah, bh[ni]);
                mma_tf32(acc[ni], ah, bl[ni]);
                mma_tf32(acc[ni], al, bh[ni]);
            }
        }
        if (t < 15) {
            *(float4*)&As[cur ^ 1][kl0][d40] = xa0;
            *(float4*)&As[cur ^ 1][kl1][d41] = xa1;
            *(float4*)&Bs[cur ^ 1][kl0][d40] = hb0;
            *(float4*)&Bs[cur ^ 1][kl1][d41] = hb1;
        }
        __syncthreads();
    }
    size_t base = ((size_t)(ks * 64 + bm)) * 4096;
#pragma unroll
    for (int ni = 0; ni < 4; ni++) {
        int d0 = rb + gid, h = vb + ni * 8 + tig * 2;
        float2 v0 = {acc[ni][0], acc[ni][1]};
        float2 v1 = {acc[ni][2], acc[ni][3]};
        *(float2*)&g_T1p[base + (size_t)d0 * 64 + h] = v0;
        *(float2*)&g_T1p[base + (size_t)(d0 + 8) * 64 + h] = v1;
    }
}

// ============ kernel C: T1 reduce; S = gelu(...); T2 = S fc2_2; sb = S.b2_2 ============
__global__ void __launch_bounds__(256)
sgen_kernel(const float* __restrict__ x,
            const float* __restrict__ f2w1, const float* __restrict__ f2b1,
            const float* __restrict__ f2w2, const float* __restrict__ f2b2)
{
    extern __shared__ float sm[];
    float* T1s  = sm;
    float* F1s  = T1s + 4160;
    float* F2s  = F1s + 4160;
    float* Ss   = F2s + 4160;
    float* xp   = Ss + 4160;
    float* xsums= xp + 256;
    float* b1s  = xsums + 64;
    float* b2s  = b1s + 64;
    int tid = threadIdx.x;
    int bm = blockIdx.x;
    int b = bm >> 3, m = bm & 7;

#pragma unroll
    for (int r = 0; r < 16; r++) {
        int o = tid + 256 * r;
        float s = 0.f;
#pragma unroll
        for (int ks = 0; ks < 4; ks++)
            s += g_T1p[((size_t)(ks * 64 + bm)) * 4096 + o];
        T1s[(o >> 6) * 65 + (o & 63)] = s;
    }
    {
        int d = tid & 63, p = tid >> 6;
        const float* xp0 = &x[(size_t)(b * LL + p * 512) * DD + m * 64 + d];
        float s = 0.f;
        for (int l = 0; l < 512; l++) s += xp0[(size_t)l * DD];
        xp[p * 64 + d] = s;
    }
    __syncthreads();
    if (tid < 64) xsums[tid] = xp[tid] + xp[64 + tid] + xp[128 + tid] + xp[192 + tid];

    int tx = tid & 15, ty = tid >> 4;
    float t2acc[4][4] = {};
    float sbacc[4] = {};
    for (int c = 0; c < 4; c++) {
        __syncthreads();
#pragma unroll
        for (int r = 0; r < 16; r++) {
            int i = tid + 256 * r;
            int khl = i >> 6, h = i & 63;
            F1s[khl * 65 + h] = f2w1[(size_t)m * 16384 + (c * 64 + khl) * 64 + h];
            F2s[khl * 65 + h] = f2w2[(size_t)m * 16384 + (c * 64 + khl) * 64 + h];
        }
        if (tid < 64) {
            b1s[tid] = f2b1[m * 256 + c * 64 + tid];
            b2s[tid] = f2b2[m * 256 + c * 64 + tid];
        }
        __syncthreads();
        float spre[4][4] = {};
#pragma unroll 8
        for (int h = 0; h < 64; h++) {
            float tv[4], fv[4];
#pragma unroll
            for (int ii = 0; ii < 4; ii++) tv[ii] = T1s[(ty * 4 + ii) * 65 + h];
#pragma unroll
            for (int jj = 0; jj < 4; jj++) fv[jj] = F1s[(tx * 4 + jj) * 65 + h];
#pragma unroll
            for (int ii = 0; ii < 4; ii++)
#pragma unroll
                for (int jj = 0; jj < 4; jj++)
                    spre[ii][jj] += tv[ii] * fv[jj];
        }
#pragma unroll
        for (int ii = 0; ii < 4; ii++)
#pragma unroll
            for (int jj = 0; jj < 4; jj++) {
                int d = ty * 4 + ii, khl = tx * 4 + jj;
                Ss[d * 65 + khl] = geluf(spre[ii][jj] + xsums[d] * b1s[khl]);
            }
        __syncthreads();
#pragma unroll 8
        for (int khl = 0; khl < 64; khl++) {
            float sv[4], fv[4];
#pragma unroll
            for (int ii = 0; ii < 4; ii++) sv[ii] = Ss[(ty * 4 + ii) * 65 + khl];
#pragma unroll
            for (int jj = 0; jj < 4; jj++) fv[jj] = F2s[khl * 65 + tx * 4 + jj];
#pragma unroll
            for (int ii = 0; ii < 4; ii++)
#pragma unroll
                for (int jj = 0; jj < 4; jj++)
                    t2acc[ii][jj] += sv[ii] * fv[jj];
            if (tx == 0) {
                float bv = b2s[khl];
#pragma unroll
                for (int ii = 0; ii < 4; ii++) sbacc[ii] += sv[ii] * bv;
            }
        }
    }
#pragma unroll
    for (int ii = 0; ii < 4; ii++)
#pragma unroll
        for (int jj = 0; jj < 4; jj++)
            g_T2[(size_t)bm * 4096 + (ty * 4 + ii) * 64 + tx * 4 + jj] = t2acc[ii][jj];
    if (tx == 0)
#pragma unroll
        for (int ii = 0; ii < 4; ii++) g_sb[bm * 64 + ty * 4 + ii] = sbacc[ii];
}

// ============ kernel E: mixpre = H2 @ T2^T + sb — 3xTF32 mma (R6 version) ============
__global__ void __launch_bounds__(256)
mixpre_mma()
{
    extern __shared__ float sm[];
    float* Hs  = sm;                // [128][68]
    float* Ts  = Hs + 128 * 68;     // [64][68]  [d][h]
    float* Cs  = Ts + 64 * 68;      // [64][68]
    float* sbs = Cs + 64 * 68;      // 64
    int tid = threadIdx.x;
    int l0 = blockIdx.x * 128;
    int bm = blockIdx.y;
    int b = bm >> 3, m = bm & 7;

    {
        int f4 = (tid & 15) * 4, r = tid >> 4;
#pragma unroll
        for (int it = 0; it < 8; it++) {
            int row = r + it * 16;
            *(float4*)&Hs[row * 68 + f4] =
                *(const float4*)&g_H2[((size_t)bm * LL + l0 + row) * 64 + f4];
        }
#pragma unroll
        for (int it = 0; it < 4; it++) {
            int dd = r + it * 16;
            *(float4*)&Ts[dd * 68 + f4] = *(const float4*)&g_T2[(size_t)bm * 4096 + dd * 64 + f4];
        }
        if (tid < 64) sbs[tid] = g_sb[bm * 64 + tid];
    }
    __syncthreads();

    int warp = tid >> 5, lane = tid & 31, gid = lane >> 2, tig = lane & 3;
    int mw = warp & 3, nw = warp >> 2;
    int rb = mw * 32, vb = nw * 32;

    float acc[2][4][4] = {};
#pragma unroll
    for (int kk = 0; kk < 64; kk += 8) {
        uint32_t ah[2][4], al[2][4];
#pragma unroll
        for (int mi = 0; mi < 2; mi++) {
            int rr = rb + mi * 16;
            split3(Hs[(rr + gid) * 68 + kk + tig],     ah[mi][0], al[mi][0]);
            split3(Hs[(rr + gid + 8) * 68 + kk + tig], ah[mi][1], al[mi][1]);
            split3(Hs[(rr + gid) * 68 + kk + tig + 4],     ah[mi][2], al[mi][2]);
            split3(Hs[(rr + gid + 8) * 68 + kk + tig + 4], ah[mi][3], al[mi][3]);
        }
        uint32_t bh[4][2], bl[4][2];
#pragma unroll
        for (int ni = 0; ni < 4; ni++) {
            int cc = vb + ni * 8 + gid;
            split3(Ts[cc * 68 + kk + tig],     bh[ni][0], bl[ni][0]);
            split3(Ts[cc * 68 + kk + tig + 4], bh[ni][1], bl[ni][1]);
        }
#pragma unroll
        for (int mi = 0; mi < 2; mi++)
#pragma unroll
            for (int ni = 0; ni < 4; ni++) {
                mma_tf32(acc[mi][ni], ah[mi], bh[ni]);
                mma_tf32(acc[mi][ni], ah[mi], bl[ni]);
                mma_tf32(acc[mi][ni], al[mi], bh[ni]);
            }
    }
#pragma unroll
    for (int p = 0; p < 2; p++) {
        if ((mw >> 1) == p) {
            int lr = (mw & 1) * 32;
#pragma unroll
            for (int mi = 0; mi < 2; mi++)
#pragma unroll
                for (int ni = 0; ni < 4; ni++) {
                    int rr = lr + mi * 16 + gid;
                    int cc = vb + ni * 8 + tig * 2;
                    Cs[rr * 68 + cc]           = acc[mi][ni][0] + sbs[cc];
                    Cs[rr * 68 + cc + 1]       = acc[mi][ni][1] + sbs[cc + 1];
                    Cs[(rr + 8) * 68 + cc]     = acc[mi][ni][2] + sbs[cc];
                    Cs[(rr + 8) * 68 + cc + 1] = acc[mi][ni][3] + sbs[cc + 1];
                }
        }
        __syncthreads();
#pragma unroll
        for (int it = 0; it < 4; it++) {
            int idx = tid + 256 * it;
            int row = idx >> 4, c4 = (idx & 15) * 4;
            *(float4*)&g_mixpre[(size_t)(b * LL + l0 + p * 64 + row) * DD + m * 64 + c4] =
                *(float4*)&Cs[row * 68 + c4];
        }
        __syncthreads();
    }
}

// ---------------- LN helpers ----------------
__device__ __forceinline__ float blk_sum128(float v, float* sbuf)
{
#pragma unroll
    for (int o = 16; o; o >>= 1) v += __shfl_xor_sync(0xffffffffu, v, o);
    __syncthreads();
    if ((threadIdx.x & 31) == 0) sbuf[threadIdx.x >> 5] = v;
    __syncthreads();
    return sbuf[0] + sbuf[1] + sbuf[2] + sbuf[3];
}

__global__ void __launch_bounds__(128)
ln_mix_kernel(const float* __restrict__ g1, const float* __restrict__ b1,
              const float* __restrict__ g2, const float* __restrict__ b2)
{
    __shared__ float sbuf[4];
    size_t row = blockIdx.x;
    int t = threadIdx.x;
    const float* r = g_mixpre + row * DD;
    float v[4];
#pragma unroll
    for (int i = 0; i < 4; i++) v[i] = r[t + 128 * i];
    float mean = blk_sum128(v[0] + v[1] + v[2] + v[3], sbuf) * (1.0f / 512.0f);
    float sq = 0.f;
#pragma unroll
    for (int i = 0; i < 4; i++) { float d = v[i] - mean; sq += d * d; }
    float var = blk_sum128(sq, sbuf) * (1.0f / 512.0f);
    float inv = rsqrtf(var + 1e-5f);
    float mx[4];
#pragma unroll
    for (int i = 0; i < 4; i++) {
        int c = t + 128 * i;
        mx[i] = (v[i] - mean) * inv * g1[c] + b1[c];
        g_mix[row * DD + c] = mx[i];
    }
    float mean2 = blk_sum128(mx[0] + mx[1] + mx[2] + mx[3], sbuf) * (1.0f / 512.0f);
    float sq2 = 0.f;
#pragma unroll
    for (int i = 0; i < 4; i++) { float d = mx[i] - mean2; sq2 += d * d; }
    float var2 = blk_sum128(sq2, sbuf) * (1.0f / 512.0f);
    float inv2 = rsqrtf(var2 + 1e-5f);
#pragma unroll
    for (int i = 0; i < 4; i++) {
        int c = t + 128 * i;
        g_u[row * DD + c] = (mx[i] - mean2) * inv2 * g2[c] + b2[c];
    }
}

// ============ bottleneck 1x1 + GLU via tf32 mma — double-buffered, raw operands ============
__global__ void __launch_bounds__(256)
bneck_glu_mma(const float* __restrict__ bw, const float* __restrict__ bb)
{
    __shared__ float As[2][16][132];
    __shared__ float Bs[2][16][132];
    __shared__ float Cs[32][68];
    int tid = threadIdx.x;
    int warp = tid >> 5, lane = tid & 31;
    int mw = warp & 3, nw = warp >> 2;
    int gid = lane >> 2, tig = lane & 3;
    int r0 = blockIdx.y * 128, n0 = blockIdx.x * 64;

    float acc[2][8][4] = {};

    int arow = tid >> 1;
    int akq  = (tid & 1) * 8;
    int vcol = tid >> 1;
    int brr  = (vcol & 1) ? (512 + n0 + (vcol >> 1)) : (n0 + (vcol >> 1));

    const float* pA = &g_u[(size_t)(r0 + arow) * 512 + akq];
    const float* pB = &bw[(size_t)brr * 512 + akq];

    float ar[8], br[8];
    *(float4*)&ar[0] = *(const float4*)pA;
    *(float4*)&ar[4] = *(const float4*)(pA + 4);
    *(float4*)&br[0] = *(const float4*)pB;
    *(float4*)&br[4] = *(const float4*)(pB + 4);
#pragma unroll
    for (int j = 0; j < 8; j++) {
        As[0][akq + j][arow] = ar[j];
        Bs[0][akq + j][vcol] = br[j];
    }
    __syncthreads();

    for (int t = 0; t < 32; t++) {
        int cur = t & 1;
        if (t < 31) {
            const float* qA = pA + (t + 1) * 16;
            const float* qB = pB + (t + 1) * 16;
            *(float4*)&ar[0] = *(const float4*)qA;
            *(float4*)&ar[4] = *(const float4*)(qA + 4);
            *(float4*)&br[0] = *(const float4*)qB;
            *(float4*)&br[4] = *(const float4*)(qB + 4);
        }
#pragma unroll
        for (int kk = 0; kk < 16; kk += 8) {
            uint32_t a[2][4];
#pragma unroll
            for (int mi = 0; mi < 2; mi++) {
                int rb = mw * 32 + mi * 16;
                a[mi][0] = __float_as_uint(As[cur][kk + tig][rb + gid]);
                a[mi][1] = __float_as_uint(As[cur][kk + tig][rb + gid + 8]);
                a[mi][2] = __float_as_uint(As[cur][kk + tig + 4][rb + gid]);
                a[mi][3] = __float_as_uint(As[cur][kk + tig + 4][rb + gid + 8]);
            }
            uint32_t bfr[8][2];
#pragma unroll
            for (int ni = 0; ni < 8; ni++) {
                int vb = nw * 64 + ni * 8;
                bfr[ni][0] = __float_as_uint(Bs[cur][kk + tig][vb + gid]);
                bfr[ni][1] = __float_as_uint(Bs[cur][kk + tig + 4][vb + gid]);
            }
#pragma unroll
            for (int mi = 0; mi < 2; mi++)
#pragma unroll
                for (int ni = 0; ni < 8; ni++)
                    mma_tf32(acc[mi][ni], a[mi], bfr[ni]);
        }
        if (t < 31) {
#pragma unroll
            for (int j = 0; j < 8; j++) {
                As[cur ^ 1][akq + j][arow] = ar[j];
                Bs[cur ^ 1][akq + j][vcol] = br[j];
            }
        }
        __syncthreads();
    }

    float bbA[8], bbB[8];
#pragma unroll
    for (int ni = 0; ni < 8; ni++) {
        int cR = n0 + nw * 32 + ni * 4 + tig;
        bbA[ni] = bb[cR];
        bbB[ni] = bb[512 + cR];
    }
    for (int p = 0; p < 4; p++) {
        if (mw == p) {
#pragma unroll
            for (int mi = 0; mi < 2; mi++)
#pragma unroll
                for (int ni = 0; ni < 8; ni++) {
                    int cc = nw * 32 + ni * 4 + tig;
                    float ga0 = acc[mi][ni][0] + bbA[ni];
                    float gb0 = acc[mi][ni][1] + bbB[ni];
                    float ga1 = acc[mi][ni][2] + bbA[ni];
                    float gb1 = acc[mi][ni][3] + bbB[ni];
                    Cs[mi * 16 + gid][cc]     = ga0 * sigmoidf_(gb0);
                    Cs[mi * 16 + gid + 8][cc] = ga1 * sigmoidf_(gb1);
                }
        }
        __syncthreads();
        {
            int row = tid >> 3, c = (tid & 7) * 8;
            float4 v0 = *(float4*)&Cs[row][c];
            float4 v1 = *(float4*)&Cs[row][c + 4];
            float* op = &g_c0[(size_t)(r0 + p * 32 + row) * 512 + n0 + c];
            *(float4*)op = v0;
            *(float4*)(op + 4) = v1;
        }
        __syncthreads();
    }
}

// ============ depthwise conv (K=31, pad 15) — register sliding window ============
__global__ void __launch_bounds__(256)
dwconv_kernel(const float* __restrict__ dw, const float* __restrict__ dwb)
{
    __shared__ float ins[158 * 64];
    __shared__ float wts[64 * 31];
    __shared__ float bs[64];
    int tid = threadIdx.x;
    int c0 = blockIdx.x * 64;
    int l0 = blockIdx.y * 128;
    int b  = blockIdx.z;
    for (int i = tid; i < 158 * 64; i += 256) {
        int rr = i >> 6, c = i & 63;
        int l = l0 - 15 + rr;
        ins[i] = (l >= 0 && l < LL) ? g_c0[((size_t)(b * LL + l)) * DD + c0 + c] : 0.f;
    }
    for (int i = tid; i < 64 * 31; i += 256)
        wts[i] = dw[c0 * 31 + i];
    if (tid < 64) bs[tid] = dwb[c0 + tid];
    __syncthreads();
    int tx = tid & 63, ty = tid >> 6;
    float w[31];
#pragma unroll
    for (int j = 0; j < 31; j++) w[j] = wts[tx * 31 + j];
    float bias = bs[tx];
    int base = ty * 32;
    float win[31];
#pragma unroll
    for (int j = 0; j < 30; j++) win[j] = ins[(base + j) * 64 + tx];
#pragma unroll
    for (int li = 0; li < 32; li++) {
        win[30] = ins[(base + li + 30) * 64 + tx];
        float acc = bias;
#pragma unroll
        for (int j = 0; j < 31; j++) acc += win[j] * w[j];
        g_v[((size_t)(b * LL + l0 + base + li)) * DD + c0 + tx] = acc;
#pragma unroll
        for (int j = 0; j < 30; j++) win[j] = win[j + 1];
    }
}

// ============ LN2 + gelu ============
__global__ void __launch_bounds__(128)
ln2_gelu_kernel(const float* __restrict__ g2, const float* __restrict__ b2)
{
    __shared__ float sbuf[4];
    size_t row = blockIdx.x;
    int t = threadIdx.x;
    const float* r = g_v + row * DD;
    float v[4];
#pragma unroll
    for (int i = 0; i < 4; i++) v[i] = r[t + 128 * i];
    float mean = blk_sum128(v[0] + v[1] + v[2] + v[3], sbuf) * (1.0f / 512.0f);
    float sq = 0.f;
#pragma unroll
    for (int i = 0; i < 4; i++) { float d = v[i] - mean; sq += d * d; }
    float var = blk_sum128(sq, sbuf) * (1.0f / 512.0f);
    float inv = rsqrtf(var + 1e-5f);
#pragma unroll
    for (int i = 0; i < 4; i++) {
        int c = t + 128 * i;
        g_w[row * DD + c] = geluf((v[i] - mean) * inv * g2[c] + b2[c]);
    }
}

// ============ final linear + bias + residual via tf32 mma — double-buffered, raw operands ============
__global__ void __launch_bounds__(256)
linear_res_mma(const float* __restrict__ lw, const float* __restrict__ lb,
               float* __restrict__ out)
{
    extern __shared__ float smd[];
    float* Asd = smd;
    float* Bsd = smd + 4224;
    float* Csd = smd + 8448;
#define LAS(bf, k, r) Asd[(bf) * 2112 + (k) * 132 + (r)]
#define LBS(bf, k, r) Bsd[(bf) * 2112 + (k) * 132 + (r)]
    int tid = threadIdx.x;
    int warp = tid >> 5, lane = tid & 31;
    int mw = warp & 3, nw = warp >> 2;
    int gid = lane >> 2, tig = lane & 3;
    int r0 = blockIdx.y * 128, n0 = blockIdx.x * 128;

    float acc[2][8][4] = {};

    int arow = tid >> 1;
    int akq  = (tid & 1) * 8;

    const float* pA = &g_w[(size_t)(r0 + arow) * 512 + akq];
    const float* pB = &lw[(size_t)(n0 + arow) * 512 + akq];

    float ar[8], br[8];
    *(float4*)&ar[0] = *(const float4*)pA;
    *(float4*)&ar[4] = *(const float4*)(pA + 4);
    *(float4*)&br[0] = *(const float4*)pB;
    *(float4*)&br[4] = *(const float4*)(pB + 4);
#pragma unroll
    for (int j = 0; j < 8; j++) {
        LAS(0, akq + j, arow) = ar[j];
        LBS(0, akq + j, arow) = br[j];
    }
    __syncthreads();

    for (int t = 0; t < 32; t++) {
        int cur = t & 1;
        if (t < 31) {
            const float* qA = pA + (t + 1) * 16;
            const float* qB = pB + (t + 1) * 16;
            *(float4*)&ar[0] = *(const float4*)qA;
            *(float4*)&ar[4] = *(const float4*)(qA + 4);
            *(float4*)&br[0] = *(const float4*)qB;
            *(float4*)&br[4] = *(const float4*)(qB + 4);
        }
#pragma unroll
        for (int kk = 0; kk < 16; kk += 8) {
            uint32_t a[2][4];
#pragma unroll
            for (int mi = 0; mi < 2; mi++) {
                int rb = mw * 32 + mi * 16;
                a[mi][0] = __float_as_uint(LAS(cur, kk + tig, rb + gid));
                a[mi][1] = __float_as_uint(LAS(cur, kk + tig, rb + gid + 8));
                a[mi][2] = __float_as_uint(LAS(cur, kk + tig + 4, rb + gid));
                a[mi][3] = __float_as_uint(LAS(cur, kk + tig + 4, rb + gid + 8));
            }
            uint32_t bfr[8][2];
#pragma unroll
            for (int ni = 0; ni < 8; ni++) {
                int vb = nw * 64 + ni * 8;
                bfr[ni][0] = __float_as_uint(LBS(cur, kk + tig, vb + gid));
                bfr[ni][1] = __float_as_uint(LBS(cur, kk + tig + 4, vb + gid));
            }
#pragma unroll
            for (int mi = 0; mi < 2; mi++)
#pragma unroll
                for (int ni = 0; ni < 8; ni++)
                    mma_tf32(acc[mi][ni], a[mi], bfr[ni]);
        }
        if (t < 31) {
#pragma unroll
            for (int j = 0; j < 8; j++) {
                LAS(cur ^ 1, akq + j, arow) = ar[j];
                LBS(cur ^ 1, akq + j, arow) = br[j];
            }
        }
        __syncthreads();
    }

    for (int p = 0; p < 4; p++) {
        if (mw == p) {
#pragma unroll
            for (int mi = 0; mi < 2; mi++)
#pragma unroll
                for (int ni = 0; ni < 8; ni++) {
                    int cc = nw * 64 + ni * 8 + tig * 2;
                    Csd[(mi * 16 + gid) * 132 + cc]         = acc[mi][ni][0];
                    Csd[(mi * 16 + gid) * 132 + cc + 1]     = acc[mi][ni][1];
                    Csd[(mi * 16 + gid + 8) * 132 + cc]     = acc[mi][ni][2];
                    Csd[(mi * 16 + gid + 8) * 132 + cc + 1] = acc[mi][ni][3];
                }
        }
        __syncthreads();
        {
            int row = tid >> 3, c0c = (tid & 7) * 16;
            size_t gro = (size_t)(r0 + p * 32 + row) * 512 + n0;
#pragma unroll
            for (int q = 0; q < 4; q++) {
                int c = c0c + q * 4;
                float4 v = *(float4*)&Csd[row * 132 + c];
                float4 mres = *(const float4*)&g_mix[gro + c];
                float4 bl = *(const float4*)&lb[n0 + c];
                v.x += bl.x + mres.x; v.y += bl.y + mres.y;
                v.z += bl.z + mres.z; v.w += bl.w + mres.w;
                *(float4*)&out[gro + c] = v;
            }
        }
        __syncthreads();
    }
#undef LAS
#undef LBS
}

// ---------------- launch ----------------
extern "C" void kernel_launch(void* const* d_in, const int* in_sizes, int n_in,
                              void* d_out, int out_size)
{
    (void)in_sizes; (void)n_in; (void)out_size;
    const float* x      = (const float*)d_in[0];
    const float* w1f1w  = (const float*)d_in[1];
    const float* w1f1b  = (const float*)d_in[2];
    const float* w1f2w  = (const float*)d_in[3];
    const float* w1f2b  = (const float*)d_in[4];
    const float* w2f1w  = (const float*)d_in[5];
    const float* w2f1b  = (const float*)d_in[6];
    const float* w2f2w  = (const float*)d_in[7];
    const float* w2f2b  = (const float*)d_in[8];
    const float* lnmg   = (const float*)d_in[9];
    const float* lnmb   = (const float*)d_in[10];
    const float* c1g    = (const float*)d_in[11];
    const float* c1b    = (const float*)d_in[12];
    const float* bw     = (const float*)d_in[13];
    const float* bb     = (const float*)d_in[14];
    const float* dww    = (const float*)d_in[15];
    const float* dwb    = (const float*)d_in[16];
    const float* c2g    = (const float*)d_in[17];
    const float* c2b    = (const float*)d_in[18];
    const float* lw     = (const float*)d_in[19];
    const float* lb     = (const float*)d_in[20];
    float* out = (float*)d_out;

    const int SGEN_SMEM = (4 * 4160 + 256 + 64 + 64 + 64) * 4;
    const int FC1_SMEM  = (128 * 68 + 64 * 68 * 3 + 128) * 4;      // 87,552 B
    const int MIX_SMEM  = (128 * 68 + 64 * 68 * 2 + 64) * 4;       // 69,888 B
    const int LIN_SMEM  = (2 * 2112 * 2 + 32 * 132) * 4;           // 50,688 B
    cudaFuncSetAttribute(sgen_kernel, cudaFuncAttributeMaxDynamicSharedMemorySize, SGEN_SMEM);
    cudaFuncSetAttribute(fc1_mma, cudaFuncAttributeMaxDynamicSharedMemorySize, FC1_SMEM);
    cudaFuncSetAttribute(mixpre_mma, cudaFuncAttributeMaxDynamicSharedMemorySize, MIX_SMEM);
    cudaFuncSetAttribute(linear_res_mma, cudaFuncAttributeMaxDynamicSharedMemorySize, LIN_SMEM);

    fc1_mma<<<dim3(16, 64), 256, FC1_SMEM>>>(x, w1f1w, w1f1b, w2f1w, w2f1b);
    t1_mma<<<dim3(4, 64), 256>>>(x);
    sgen_kernel<<<64, 256, SGEN_SMEM>>>(x, w1f2w, w1f2b, w2f2w, w2f2b);
    mixpre_mma<<<dim3(16, 64), 256, MIX_SMEM>>>();
    ln_mix_kernel<<<BB * LL, 128>>>(lnmg, lnmb, c1g, c1b);
    bneck_glu_mma<<<dim3(8, 128), 256>>>(bw, bb);
    dwconv_kernel<<<dim3(8, 16, 8), 256>>>(dww, dwb);
    ln2_gelu_kernel<<<BB * LL, 128>>>(c2g, c2b);
    linear_res_mma<<<dim3(4, 128), 256, LIN_SMEM>>>(lw, lb, out);
}